// round 6
// baseline (speedup 1.0000x reference)
#include <cuda_runtime.h>
#include <cstdint>
#include <math.h>

#define SEQ 2048
#define HID 2048
#define NB  2
#define NH  16
#define HD  128
#define BH  (NB*NH)          // 32
#define MTOT (NB*SEQ)        // 4096
#define NEGMASK (-(1<<20))

// ---------------- device scratch (no allocation allowed) ----------------
__device__ int g_flag[9];                          // per-input dtype: 0=int32,1=float32,2=int8
__device__ unsigned g_x4[MTOT * (HID/4)];          // x packed u8x4   [4096][512]
__device__ int g_b32[4 * HID];                     // canonical i32 biases
__device__ unsigned g_wt[4 * HID * (HID/4)];       // w transposed+packed [n][k/4] (q,k,v,o)
__device__ int g_q[BH * SEQ * HD];                 // [bh][s][d]
__device__ int g_k[BH * SEQ * HD];
__device__ int g_v[BH * SEQ * HD];
__device__ int g_ctx[MTOT * HID];                  // [b*s][h*128+d]

// ---------------- IMMA helpers ----------------
__device__ __forceinline__ void mma_u8s8(int* d, const unsigned* a, const unsigned* b) {
    asm volatile(
        "mma.sync.aligned.m16n8k32.row.col.s32.u8.s8.s32 "
        "{%0,%1,%2,%3},{%4,%5,%6,%7},{%8,%9},{%0,%1,%2,%3};"
        : "+r"(d[0]), "+r"(d[1]), "+r"(d[2]), "+r"(d[3])
        : "r"(a[0]), "r"(a[1]), "r"(a[2]), "r"(a[3]), "r"(b[0]), "r"(b[1]));
}
__device__ __forceinline__ void mma_u8u8(int* d, const unsigned* a, const unsigned* b) {
    asm volatile(
        "mma.sync.aligned.m16n8k32.row.col.s32.u8.u8.s32 "
        "{%0,%1,%2,%3},{%4,%5,%6,%7},{%8,%9},{%0,%1,%2,%3};"
        : "+r"(d[0]), "+r"(d[1]), "+r"(d[2]), "+r"(d[3])
        : "r"(a[0]), "r"(a[1]), "r"(a[2]), "r"(a[3]), "r"(b[0]), "r"(b[1]));
}
__device__ __forceinline__ void mma_s8u8(int* d, const unsigned* a, const unsigned* b) {
    asm volatile(
        "mma.sync.aligned.m16n8k32.row.col.s32.s8.u8.s32 "
        "{%0,%1,%2,%3},{%4,%5,%6,%7},{%8,%9},{%0,%1,%2,%3};"
        : "+r"(d[0]), "+r"(d[1]), "+r"(d[2]), "+r"(d[3])
        : "r"(a[0]), "r"(a[1]), "r"(a[2]), "r"(a[3]), "r"(b[0]), "r"(b[1]));
}
__device__ __forceinline__ void ldsm_x4(unsigned* r, unsigned addr) {
    asm volatile("ldmatrix.sync.aligned.m8n8.x4.shared.b16 {%0,%1,%2,%3},[%4];"
                 : "=r"(r[0]), "=r"(r[1]), "=r"(r[2]), "=r"(r[3]) : "r"(addr));
}
__device__ __forceinline__ void ldsm_x2(unsigned* r, unsigned addr) {
    asm volatile("ldmatrix.sync.aligned.m8n8.x2.shared.b16 {%0,%1},[%2];"
                 : "=r"(r[0]), "=r"(r[1]) : "r"(addr));
}

// limb (byte-plane) extraction of 4 consecutive int32 -> one packed u32 per plane
__device__ __forceinline__ unsigned plane4(int4 v, int l) {
    unsigned sel = (unsigned)l | ((unsigned)(l + 4) << 4);
    unsigned t0 = __byte_perm((unsigned)v.x, (unsigned)v.y, sel);
    unsigned t1 = __byte_perm((unsigned)v.z, (unsigned)v.w, sel);
    return __byte_perm(t0, t1, 0x5410);
}

// ---------------- dtype detection ----------------
__device__ __forceinline__ int classify_word(unsigned w) {
    if (w == 0u) return -1;
    int iv = (int)w;
    if (iv >= -520 && iv <= 520) return 0;
    float f = __int_as_float(w);
    if (isfinite(f) && fabsf(f) <= 520.0f && f != 0.0f && f == rintf(f)) return 1;
    return 2;
}

__global__ void detect_kernel(const void* p0, const void* p1, const void* p2,
                              const void* p3, const void* p4, const void* p5,
                              const void* p6, const void* p7, const void* p8) {
    const void* ptrs[9] = {p0,p1,p2,p3,p4,p5,p6,p7,p8};
    int b = blockIdx.x;
    const unsigned* w = (const unsigned*)ptrs[b];
    int n = (b == 2 || b == 4 || b == 6 || b == 8) ? 512 : 1024;
    __shared__ int votes[3];
    if (threadIdx.x < 3) votes[threadIdx.x] = 0;
    __syncthreads();
    int local[3] = {0,0,0};
    for (int i = threadIdx.x; i < n; i += blockDim.x) {
        int c = classify_word(w[i]);
        if (c >= 0) local[c]++;
    }
    for (int c = 0; c < 3; c++) if (local[c]) atomicAdd(&votes[c], local[c]);
    __syncthreads();
    if (threadIdx.x == 0) {
        int best = 0;
        if (votes[1] > votes[best]) best = 1;
        if (votes[2] > votes[best]) best = 2;
        g_flag[b] = best;
    }
}

// ---------------- canonicalize x -> u8x4 words ----------------
__global__ void conv_x_kernel(const void* __restrict__ xp) {
    int i = blockIdx.x * blockDim.x + threadIdx.x;
    if (i >= MTOT * (HID/4)) return;
    int flag = g_flag[0];
    unsigned a, b, c, d;
    if (flag == 1) {
        float4 v = reinterpret_cast<const float4*>(xp)[i];
        a = (unsigned)(int)v.x; b = (unsigned)(int)v.y;
        c = (unsigned)(int)v.z; d = (unsigned)(int)v.w;
    } else {
        int4 v = reinterpret_cast<const int4*>(xp)[i];
        a = (unsigned)v.x; b = (unsigned)v.y; c = (unsigned)v.z; d = (unsigned)v.w;
    }
    g_x4[i] = (a & 255u) | ((b & 255u) << 8) | ((c & 255u) << 16) | ((d & 255u) << 24);
}

// ---------------- fused convert + transpose + pack weights ----------------
__global__ void convpack_w_kernel(const void* w0, const void* w1, const void* w2, const void* w3) {
    int i = blockIdx.x * blockDim.x + threadIdx.x;
    if (i >= HID * (HID/4)) return;
    int slot = blockIdx.y;
    const void* ws[4] = {w0, w1, w2, w3};
    const void* wp = ws[slot];
    int flag = g_flag[1 + slot*2];
    int kw = i >> 11;          // 0..511
    int n  = i & (HID-1);      // 0..2047
    unsigned b[4];
    if (flag == 2) {
        const unsigned char* p = (const unsigned char*)wp;
#pragma unroll
        for (int j = 0; j < 4; j++) b[j] = p[(size_t)(4*kw+j)*HID + n];
    } else if (flag == 1) {
        const float* p = (const float*)wp;
#pragma unroll
        for (int j = 0; j < 4; j++) b[j] = (unsigned)(int)p[(size_t)(4*kw+j)*HID + n] & 255u;
    } else {
        const int* p = (const int*)wp;
#pragma unroll
        for (int j = 0; j < 4; j++) b[j] = (unsigned)p[(size_t)(4*kw+j)*HID + n] & 255u;
    }
    g_wt[(size_t)slot * (HID*(HID/4)) + (size_t)n*(HID/4) + kw] =
        b[0] | (b[1]<<8) | (b[2]<<16) | (b[3]<<24);
}

// ---------------- canonicalize all biases -> i32 ----------------
__global__ void conv_b_kernel(const void* b0, const void* b1, const void* b2, const void* b3) {
    int i = blockIdx.x * blockDim.x + threadIdx.x;
    if (i >= HID) return;
    int slot = blockIdx.y;
    const void* bs[4] = {b0, b1, b2, b3};
    int flag = g_flag[2 + slot*2];
    int v;
    if (flag == 1) v = (int)reinterpret_cast<const float*>(bs[slot])[i];
    else           v = reinterpret_cast<const int*>(bs[slot])[i];
    g_b32[slot * HID + i] = v;
}

// ---------------- QKV projection via IMMA (u8 x s8, exact), all 3 slots ----------------
__global__ __launch_bounds__(256) void proj_imma_kernel() {
    __shared__ unsigned char As[128*80];
    __shared__ unsigned char Bs[128*80];
    int slot = blockIdx.z;
    const unsigned* W4 = g_wt + (size_t)slot * (HID*(HID/4));
    const int* bias = g_b32 + slot * HID;
    int* outp = (slot == 0) ? g_q : (slot == 1) ? g_k : g_v;

    int bn = blockIdx.x;   // 0..15
    int bm = blockIdx.y;   // 0..31
    int t = threadIdx.x, lane = t & 31, warp = t >> 5;
    int wm = warp >> 2, wn = warp & 3;

    unsigned aBase = (unsigned)__cvta_generic_to_shared(As);
    unsigned bBase = (unsigned)__cvta_generic_to_shared(Bs);

    int acc[4][4][4];
#pragma unroll
    for (int i = 0; i < 4; i++)
#pragma unroll
        for (int j = 0; j < 4; j++)
#pragma unroll
            for (int r = 0; r < 4; r++) acc[i][j][r] = 0;

    int lrowA = (lane & 7) + ((lane >> 3) & 1) * 8;
    int lkoffA = (lane >= 16) ? 16 : 0;
    int lrowB = (lane & 7);
    int lkoffB = ((lane >> 3) & 1) * 16;

    for (int ks = 0; ks < 32; ks++) {
        for (int idx = t; idx < 512; idx += 256) {
            int row = idx >> 2, q = idx & 3;
            int4 v = *reinterpret_cast<const int4*>(&g_x4[(size_t)(bm*128 + row)*512 + ks*16 + q*4]);
            *reinterpret_cast<int4*>(As + row*80 + q*16) = v;
            int4 w = *reinterpret_cast<const int4*>(&W4[(size_t)(bn*128 + row)*512 + ks*16 + q*4]);
            *reinterpret_cast<int4*>(Bs + row*80 + q*16) = w;
        }
        __syncthreads();
#pragma unroll
        for (int kk = 0; kk < 2; kk++) {
            unsigned bfr[4][2];
#pragma unroll
            for (int nf = 0; nf < 4; nf++)
                ldsm_x2(bfr[nf], bBase + (wn*32 + nf*8 + lrowB)*80 + kk*32 + lkoffB);
            unsigned afr[4][4];
#pragma unroll
            for (int mf = 0; mf < 4; mf++)
                ldsm_x4(afr[mf], aBase + (wm*64 + mf*16 + lrowA)*80 + kk*32 + lkoffA);
#pragma unroll
            for (int mf = 0; mf < 4; mf++)
#pragma unroll
                for (int nf = 0; nf < 4; nf++)
                    mma_u8s8(acc[mf][nf], afr[mf], bfr[nf]);
        }
        __syncthreads();
    }

#pragma unroll
    for (int mf = 0; mf < 4; mf++) {
#pragma unroll
        for (int nf = 0; nf < 4; nf++) {
            int n = bn*128 + wn*32 + nf*8 + 2*(lane & 3);
            int h = n >> 7, d = n & (HD-1);
            int bia0 = bias[n], bia1 = bias[n+1];
#pragma unroll
            for (int half = 0; half < 2; half++) {
                int r = bm*128 + wm*64 + mf*16 + (lane >> 2) + half*8;
                int b = r >> 11, s = r & (SEQ-1);
                int v0 = (acc[mf][nf][half*2+0] + bia0) >> 6;
                int v1 = (acc[mf][nf][half*2+1] + bia1) >> 6;
                *reinterpret_cast<int2*>(&outp[((size_t)(b*NH + h)*SEQ + s)*HD + d]) = make_int2(v0, v1);
            }
        }
    }
}

// ---------------- fused attention via limb IMMA ----------------
// smem: scores int[16][2048] (131072B), Qp 3x16x144 (6912B), Kp 3x128x144 (55296B)
#define QP_OFF   131072
#define QP_STR   2304          // 16*144
#define KP_OFF   (QP_OFF + 3*QP_STR)     // 137984
#define KP_STR   18432         // 128*144
#define ATTN_SMEM (KP_OFF + 3*KP_STR)    // 193280

__global__ __launch_bounds__(256, 1) void attn_kernel() {
    extern __shared__ int smem[];
    int* scores = smem;
    unsigned char* sbytes = (unsigned char*)smem;

    int t = threadIdx.x, lane = t & 31, warp = t >> 5;
    int q0 = (gridDim.x - 1 - blockIdx.x) * 16;    // long blocks first
    int bh = blockIdx.y;
    const int* Qb = g_q + (size_t)bh * SEQ * HD;
    const int* Kb = g_k + (size_t)bh * SEQ * HD;
    const int* Vb = g_v + (size_t)bh * SEQ * HD;

    unsigned smemBase = (unsigned)__cvta_generic_to_shared(smem);
    unsigned qBase = smemBase + QP_OFF;
    unsigned kBase = smemBase + KP_OFF;

    // ---- stage Q limb planes (byte planes of int32; limb2 valid as s8 since |q| < 2^23) ----
    for (int i = t; i < 16*32; i += 256) {
        int row = i >> 5, g = i & 31;
        int4 v = *reinterpret_cast<const int4*>(&Qb[(q0 + row)*HD + g*4]);
#pragma unroll
        for (int l = 0; l < 3; l++)
            *reinterpret_cast<unsigned*>(sbytes + QP_OFF + l*QP_STR + row*144 + g*4) = plane4(v, l);
    }
    __syncthreads();

    int lrowA = (lane & 7) + ((lane >> 3) & 1) * 8;
    int lkoffA = (lane >= 16) ? 16 : 0;
    int lrowB = (lane & 7);
    int lkoffB = ((lane >> 3) & 1) * 16;

    int ntiles = q0 / 128 + 1;
    for (int tile = 0; tile < ntiles; tile++) {
        int kt0 = tile * 128;
        // ---- stage K limb planes for this tile ----
        for (int i = t; i < 128*32; i += 256) {
            int key = i >> 5, g = i & 31;
            int4 v = *reinterpret_cast<const int4*>(&Kb[(kt0 + key)*HD + g*4]);
#pragma unroll
            for (int l = 0; l < 3; l++)
                *reinterpret_cast<unsigned*>(sbytes + KP_OFF + l*KP_STR + key*144 + g*4) = plane4(v, l);
        }
        __syncthreads();

        // ---- 8 limb-pair GEMMs: warp covers keys [warp*16, warp*16+16) ----
        int a00[2][4], a01[2][4], a02[2][4], a10[2][4], a11[2][4], a12[2][4], a20[2][4], a21[2][4];
#pragma unroll
        for (int nf = 0; nf < 2; nf++)
#pragma unroll
            for (int e = 0; e < 4; e++) {
                a00[nf][e]=0; a01[nf][e]=0; a02[nf][e]=0; a10[nf][e]=0;
                a11[nf][e]=0; a12[nf][e]=0; a20[nf][e]=0; a21[nf][e]=0;
            }

#pragma unroll
        for (int kc = 0; kc < 4; kc++) {
            unsigned A[3][4];
#pragma unroll
            for (int l = 0; l < 3; l++)
                ldsm_x4(A[l], qBase + l*QP_STR + lrowA*144 + kc*32 + lkoffA);
            unsigned B[3][2][2];
#pragma unroll
            for (int l = 0; l < 3; l++)
#pragma unroll
                for (int nf = 0; nf < 2; nf++)
                    ldsm_x2(B[l][nf], kBase + l*KP_STR + (warp*16 + nf*8 + lrowB)*144 + kc*32 + lkoffB);
#pragma unroll
            for (int nf = 0; nf < 2; nf++) {
                mma_u8u8(a00[nf], A[0], B[0][nf]);
                mma_u8u8(a01[nf], A[0], B[1][nf]);
                mma_u8s8(a02[nf], A[0], B[2][nf]);
                mma_u8u8(a10[nf], A[1], B[0][nf]);
                mma_u8u8(a11[nf], A[1], B[1][nf]);
                mma_u8s8(a12[nf], A[1], B[2][nf]);
                mma_s8u8(a20[nf], A[2], B[0][nf]);
                mma_s8u8(a21[nf], A[2], B[1][nf]);
            }
        }

        // ---- combine limbs mod 2^32, >>1, store to score strip ----
#pragma unroll
        for (int nf = 0; nf < 2; nf++)
#pragma unroll
            for (int e = 0; e < 4; e++) {
                unsigned s = (unsigned)a00[nf][e]
                    + (((unsigned)a01[nf][e] + (unsigned)a10[nf][e]) << 8)
                    + (((unsigned)a11[nf][e] + (unsigned)a02[nf][e] + (unsigned)a20[nf][e]) << 16)
                    + (((unsigned)a12[nf][e] + (unsigned)a21[nf][e]) << 24);
                int row = (lane >> 2) + (e >> 1) * 8;
                int col = warp*16 + nf*8 + 2*(lane & 3) + (e & 1);
                scores[row*SEQ + kt0 + col] = ((int)s) >> 1;
            }
        __syncthreads();
    }

    // ---- per-row max + ballot/shuffle sparse AV (warp per 2 rows, uniform trips) ----
#pragma unroll
    for (int rr = 0; rr < 2; rr++) {
        int r = warp + rr*8;
        int qr = q0 + r;
        const int* srow = scores + r*SEQ;

        // row max (uniform trip count; inactive lanes contribute INT_MIN)
        int m = (int)0x80000000;
        for (int k0 = 0; k0 <= qr; k0 += 32) {
            int k = k0 + lane;
            if (k <= qr) m = max(m, srow[k]);
        }
#pragma unroll
        for (int off = 16; off; off >>= 1) m = max(m, __shfl_xor_sync(0xffffffffu, m, off));
        bool hasMasked = (qr < SEQ - 1);
        if (hasMasked) m = max(m, NEGMASK);

        unsigned acc0 = 0, acc1 = 0, acc2 = 0, acc3 = 0;
        int d0 = lane * 4;

        // contributors: scores within 256 of row max (ballot + shfl broadcast; no list)
        for (int k0 = 0; k0 <= qr; k0 += 32) {
            int k = k0 + lane;
            int a = (k <= qr) ? (srow[k] - m + 256) : 0;
            unsigned mask = __ballot_sync(0xffffffffu, a > 0);
            while (mask) {
                int src = __ffs(mask) - 1;
                mask &= mask - 1;
                unsigned aa = (unsigned)__shfl_sync(0xffffffffu, a, src);
                int kk = k0 + src;
                int4 v = *reinterpret_cast<const int4*>(&Vb[kk*HD + d0]);
                acc0 += aa * (unsigned)v.x; acc1 += aa * (unsigned)v.y;
                acc2 += aa * (unsigned)v.z; acc3 += aa * (unsigned)v.w;
            }
        }

        // pathological: masked entries contribute (attn of masked = am > 0)
        int am = NEGMASK - m + 256;
        if (hasMasked && am > 0) {
            for (int k = qr + 1; k < SEQ; k++) {
                int4 v = *reinterpret_cast<const int4*>(&Vb[k*HD + d0]);
                unsigned ua = (unsigned)am;
                acc0 += ua * (unsigned)v.x; acc1 += ua * (unsigned)v.y;
                acc2 += ua * (unsigned)v.z; acc3 += ua * (unsigned)v.w;
            }
        }

        int b = bh >> 4, h = bh & (NH-1);
        int4 o;
        o.x = ((int)acc0) >> 12; o.y = ((int)acc1) >> 12;
        o.z = ((int)acc2) >> 12; o.w = ((int)acc3) >> 12;
        *reinterpret_cast<int4*>(&g_ctx[((size_t)(b*SEQ + qr))*HID + h*HD + d0]) = o;
    }
}

// ---------------- output projection via IMMA limbs (exact mod 2^32) ----------------
__global__ __launch_bounds__(256) void out_imma_kernel(float* __restrict__ out) {
    __shared__ unsigned char Ap[4][64*48];
    __shared__ unsigned char Bs[64*48];
    const unsigned* W4 = g_wt + (size_t)3 * (HID*(HID/4));
    const int* bias = g_b32 + 3 * HID;

    int bn = blockIdx.x;   // 0..31
    int bm = blockIdx.y;   // 0..63
    int t = threadIdx.x, lane = t & 31, warp = t >> 5;
    int wm = warp >> 2, wn = warp & 3;

    unsigned aBase[4], bBase;
#pragma unroll
    for (int l = 0; l < 4; l++) aBase[l] = (unsigned)__cvta_generic_to_shared(Ap[l]);
    bBase = (unsigned)__cvta_generic_to_shared(Bs);

    int acc[2][2][4][4];
#pragma unroll
    for (int i = 0; i < 2; i++)
#pragma unroll
        for (int j = 0; j < 2; j++)
#pragma unroll
            for (int l = 0; l < 4; l++)
#pragma unroll
                for (int r = 0; r < 4; r++) acc[i][j][l][r] = 0;

    int lrowA = (lane & 7) + ((lane >> 3) & 1) * 8;
    int lkoffA = (lane >= 16) ? 16 : 0;
    int lrowB = (lane & 7);
    int lkoffB = ((lane >> 3) & 1) * 16;

    for (int ks = 0; ks < 64; ks++) {
        for (int idx = t; idx < 512; idx += 256) {
            int row = idx >> 3, q = idx & 7;
            int4 v = *reinterpret_cast<const int4*>(&g_ctx[((size_t)(bm*64 + row))*HID + ks*32 + q*4]);
#pragma unroll
            for (int l = 0; l < 4; l++)
                *reinterpret_cast<unsigned*>(Ap[l] + row*48 + q*4) = plane4(v, l);
        }
        for (int idx = t; idx < 128; idx += 256) {
            int row = idx >> 1, q = idx & 1;
            int4 w = *reinterpret_cast<const int4*>(&W4[(size_t)(bn*64 + row)*512 + ks*8 + q*4]);
            *reinterpret_cast<int4*>(Bs + row*48 + q*16) = w;
        }
        __syncthreads();

        unsigned bfr[2][2];
#pragma unroll
        for (int nf = 0; nf < 2; nf++)
            ldsm_x2(bfr[nf], bBase + (wn*16 + nf*8 + lrowB)*48 + lkoffB);
#pragma unroll
        for (int mf = 0; mf < 2; mf++) {
#pragma unroll
            for (int l = 0; l < 4; l++) {
                unsigned afr[4];
                ldsm_x4(afr, aBase[l] + (wm*32 + mf*16 + lrowA)*48 + lkoffA);
#pragma unroll
                for (int nf = 0; nf < 2; nf++)
                    mma_u8s8(acc[mf][nf][l], afr, bfr[nf]);
            }
        }
        __syncthreads();
    }

#pragma unroll
    for (int mf = 0; mf < 2; mf++) {
#pragma unroll
        for (int nf = 0; nf < 2; nf++) {
            int n = bn*64 + wn*16 + nf*8 + 2*(lane & 3);
            unsigned bia0 = (unsigned)bias[n], bia1 = (unsigned)bias[n+1];
#pragma unroll
            for (int half = 0; half < 2; half++) {
                int r = bm*64 + wm*32 + mf*16 + (lane >> 2) + half*8;
                unsigned u0 = (unsigned)acc[mf][nf][0][half*2+0]
                            + ((unsigned)acc[mf][nf][1][half*2+0] << 8)
                            + ((unsigned)acc[mf][nf][2][half*2+0] << 16)
                            + ((unsigned)acc[mf][nf][3][half*2+0] << 24) + bia0;
                unsigned u1 = (unsigned)acc[mf][nf][0][half*2+1]
                            + ((unsigned)acc[mf][nf][1][half*2+1] << 8)
                            + ((unsigned)acc[mf][nf][2][half*2+1] << 16)
                            + ((unsigned)acc[mf][nf][3][half*2+1] << 24) + bia1;
                float2 fv = make_float2((float)(((int)u0) >> 7), (float)(((int)u1) >> 7));
                *reinterpret_cast<float2*>(&out[(size_t)r*HID + n]) = fv;
            }
        }
    }
}

// ---------------- launch ----------------
extern "C" void kernel_launch(void* const* d_in, const int* in_sizes, int n_in,
                              void* d_out, int out_size) {
    const void* x  = d_in[0];
    const void* wq = d_in[1]; const void* bq = d_in[2];
    const void* wk = d_in[3]; const void* bk = d_in[4];
    const void* wv = d_in[5]; const void* bv = d_in[6];
    const void* wo = d_in[7]; const void* bo = d_in[8];
    float* out = (float*)d_out;

    detect_kernel<<<9, 256>>>(x, wq, bq, wk, bk, wv, bv, wo, bo);                     // 1
    conv_x_kernel<<<(MTOT*(HID/4) + 255)/256, 256>>>(x);                              // 2
    convpack_w_kernel<<<dim3((HID*(HID/4) + 255)/256, 4), 256>>>(wq, wk, wv, wo);     // 3
    conv_b_kernel<<<dim3((HID + 255)/256, 4), 256>>>(bq, bk, bv, bo);                 // 4
    proj_imma_kernel<<<dim3(16, 32, 3), 256>>>();                                     // 5
    cudaFuncSetAttribute(attn_kernel, cudaFuncAttributeMaxDynamicSharedMemorySize, ATTN_SMEM);
    attn_kernel<<<dim3(SEQ/16, BH), 256, ATTN_SMEM>>>();                              // 6 (profiled)
    out_imma_kernel<<<dim3(32, 64), 256>>>(out);                                      // 7
}

// round 7
// speedup vs baseline: 1.0002x; 1.0002x over previous
#include <cuda_runtime.h>
#include <cstdint>
#include <math.h>

#define SEQ 2048
#define HID 2048
#define NB  2
#define NH  16
#define HD  128
#define BH  (NB*NH)          // 32
#define MTOT (NB*SEQ)        // 4096
#define NEGMASK (-(1<<20))

// ---------------- device scratch (no allocation allowed) ----------------
__device__ int g_flag[9];                          // per-input dtype: 0=int32,1=float32,2=int8
__device__ unsigned g_x4[MTOT * (HID/4)];          // x packed u8x4   [4096][512]
__device__ int g_b32[4 * HID];                     // canonical i32 biases
__device__ unsigned g_wt[4 * HID * (HID/4)];       // w transposed+packed [n][k/4] (q,k,v,o)
__device__ int g_q[BH * SEQ * HD];                 // [bh][s][d]
__device__ int g_k[BH * SEQ * HD];
__device__ int g_v[BH * SEQ * HD];
__device__ int g_ctx[MTOT * HID];                  // [b*s][h*128+d]

// ---------------- IMMA helpers ----------------
__device__ __forceinline__ void mma_u8s8(int* d, const unsigned* a, const unsigned* b) {
    asm volatile(
        "mma.sync.aligned.m16n8k32.row.col.s32.u8.s8.s32 "
        "{%0,%1,%2,%3},{%4,%5,%6,%7},{%8,%9},{%0,%1,%2,%3};"
        : "+r"(d[0]), "+r"(d[1]), "+r"(d[2]), "+r"(d[3])
        : "r"(a[0]), "r"(a[1]), "r"(a[2]), "r"(a[3]), "r"(b[0]), "r"(b[1]));
}
__device__ __forceinline__ void mma_u8u8(int* d, const unsigned* a, const unsigned* b) {
    asm volatile(
        "mma.sync.aligned.m16n8k32.row.col.s32.u8.u8.s32 "
        "{%0,%1,%2,%3},{%4,%5,%6,%7},{%8,%9},{%0,%1,%2,%3};"
        : "+r"(d[0]), "+r"(d[1]), "+r"(d[2]), "+r"(d[3])
        : "r"(a[0]), "r"(a[1]), "r"(a[2]), "r"(a[3]), "r"(b[0]), "r"(b[1]));
}
__device__ __forceinline__ void mma_s8u8(int* d, const unsigned* a, const unsigned* b) {
    asm volatile(
        "mma.sync.aligned.m16n8k32.row.col.s32.s8.u8.s32 "
        "{%0,%1,%2,%3},{%4,%5,%6,%7},{%8,%9},{%0,%1,%2,%3};"
        : "+r"(d[0]), "+r"(d[1]), "+r"(d[2]), "+r"(d[3])
        : "r"(a[0]), "r"(a[1]), "r"(a[2]), "r"(a[3]), "r"(b[0]), "r"(b[1]));
}
__device__ __forceinline__ void ldsm_x4(unsigned* r, unsigned addr) {
    asm volatile("ldmatrix.sync.aligned.m8n8.x4.shared.b16 {%0,%1,%2,%3},[%4];"
                 : "=r"(r[0]), "=r"(r[1]), "=r"(r[2]), "=r"(r[3]) : "r"(addr));
}
__device__ __forceinline__ void ldsm_x2(unsigned* r, unsigned addr) {
    asm volatile("ldmatrix.sync.aligned.m8n8.x2.shared.b16 {%0,%1},[%2];"
                 : "=r"(r[0]), "=r"(r[1]) : "r"(addr));
}

// limb (byte-plane) extraction of 4 consecutive int32 -> one packed u32 per plane
__device__ __forceinline__ unsigned plane4(int4 v, int l) {
    unsigned sel = (unsigned)l | ((unsigned)(l + 4) << 4);
    unsigned t0 = __byte_perm((unsigned)v.x, (unsigned)v.y, sel);
    unsigned t1 = __byte_perm((unsigned)v.z, (unsigned)v.w, sel);
    return __byte_perm(t0, t1, 0x5410);
}

// ---------------- dtype detection ----------------
__device__ __forceinline__ int classify_word(unsigned w) {
    if (w == 0u) return -1;
    int iv = (int)w;
    if (iv >= -520 && iv <= 520) return 0;
    float f = __int_as_float(w);
    if (isfinite(f) && fabsf(f) <= 520.0f && f != 0.0f && f == rintf(f)) return 1;
    return 2;
}

__global__ void detect_kernel(const void* p0, const void* p1, const void* p2,
                              const void* p3, const void* p4, const void* p5,
                              const void* p6, const void* p7, const void* p8) {
    const void* ptrs[9] = {p0,p1,p2,p3,p4,p5,p6,p7,p8};
    int b = blockIdx.x;
    const unsigned* w = (const unsigned*)ptrs[b];
    int n = (b == 2 || b == 4 || b == 6 || b == 8) ? 512 : 1024;
    __shared__ int votes[3];
    if (threadIdx.x < 3) votes[threadIdx.x] = 0;
    __syncthreads();
    int local[3] = {0,0,0};
    for (int i = threadIdx.x; i < n; i += blockDim.x) {
        int c = classify_word(w[i]);
        if (c >= 0) local[c]++;
    }
    for (int c = 0; c < 3; c++) if (local[c]) atomicAdd(&votes[c], local[c]);
    __syncthreads();
    if (threadIdx.x == 0) {
        int best = 0;
        if (votes[1] > votes[best]) best = 1;
        if (votes[2] > votes[best]) best = 2;
        g_flag[b] = best;
    }
}

// ---------------- canonicalize x -> u8x4 words ----------------
__global__ void conv_x_kernel(const void* __restrict__ xp) {
    int i = blockIdx.x * blockDim.x + threadIdx.x;
    if (i >= MTOT * (HID/4)) return;
    int flag = g_flag[0];
    unsigned a, b, c, d;
    if (flag == 1) {
        float4 v = reinterpret_cast<const float4*>(xp)[i];
        a = (unsigned)(int)v.x; b = (unsigned)(int)v.y;
        c = (unsigned)(int)v.z; d = (unsigned)(int)v.w;
    } else {
        int4 v = reinterpret_cast<const int4*>(xp)[i];
        a = (unsigned)v.x; b = (unsigned)v.y; c = (unsigned)v.z; d = (unsigned)v.w;
    }
    g_x4[i] = (a & 255u) | ((b & 255u) << 8) | ((c & 255u) << 16) | ((d & 255u) << 24);
}

// ---------------- fused convert + transpose + pack weights ----------------
__global__ void convpack_w_kernel(const void* w0, const void* w1, const void* w2, const void* w3) {
    int i = blockIdx.x * blockDim.x + threadIdx.x;
    if (i >= HID * (HID/4)) return;
    int slot = blockIdx.y;
    const void* ws[4] = {w0, w1, w2, w3};
    const void* wp = ws[slot];
    int flag = g_flag[1 + slot*2];
    int kw = i >> 11;          // 0..511
    int n  = i & (HID-1);      // 0..2047
    unsigned b[4];
    if (flag == 2) {
        const unsigned char* p = (const unsigned char*)wp;
#pragma unroll
        for (int j = 0; j < 4; j++) b[j] = p[(size_t)(4*kw+j)*HID + n];
    } else if (flag == 1) {
        const float* p = (const float*)wp;
#pragma unroll
        for (int j = 0; j < 4; j++) b[j] = (unsigned)(int)p[(size_t)(4*kw+j)*HID + n] & 255u;
    } else {
        const int* p = (const int*)wp;
#pragma unroll
        for (int j = 0; j < 4; j++) b[j] = (unsigned)p[(size_t)(4*kw+j)*HID + n] & 255u;
    }
    g_wt[(size_t)slot * (HID*(HID/4)) + (size_t)n*(HID/4) + kw] =
        b[0] | (b[1]<<8) | (b[2]<<16) | (b[3]<<24);
}

// ---------------- canonicalize all biases -> i32 ----------------
__global__ void conv_b_kernel(const void* b0, const void* b1, const void* b2, const void* b3) {
    int i = blockIdx.x * blockDim.x + threadIdx.x;
    if (i >= HID) return;
    int slot = blockIdx.y;
    const void* bs[4] = {b0, b1, b2, b3};
    int flag = g_flag[2 + slot*2];
    int v;
    if (flag == 1) v = (int)reinterpret_cast<const float*>(bs[slot])[i];
    else           v = reinterpret_cast<const int*>(bs[slot])[i];
    g_b32[slot * HID + i] = v;
}

// ---------------- QKV projection via IMMA (u8 x s8, exact), all 3 slots ----------------
__global__ __launch_bounds__(256) void proj_imma_kernel() {
    __shared__ unsigned char As[128*80];
    __shared__ unsigned char Bs[128*80];
    int slot = blockIdx.z;
    const unsigned* W4 = g_wt + (size_t)slot * (HID*(HID/4));
    const int* bias = g_b32 + slot * HID;
    int* outp = (slot == 0) ? g_q : (slot == 1) ? g_k : g_v;

    int bn = blockIdx.x;   // 0..15
    int bm = blockIdx.y;   // 0..31
    int t = threadIdx.x, lane = t & 31, warp = t >> 5;
    int wm = warp >> 2, wn = warp & 3;

    unsigned aBase = (unsigned)__cvta_generic_to_shared(As);
    unsigned bBase = (unsigned)__cvta_generic_to_shared(Bs);

    int acc[4][4][4];
#pragma unroll
    for (int i = 0; i < 4; i++)
#pragma unroll
        for (int j = 0; j < 4; j++)
#pragma unroll
            for (int r = 0; r < 4; r++) acc[i][j][r] = 0;

    int lrowA = (lane & 7) + ((lane >> 3) & 1) * 8;
    int lkoffA = (lane >= 16) ? 16 : 0;
    int lrowB = (lane & 7);
    int lkoffB = ((lane >> 3) & 1) * 16;

    for (int ks = 0; ks < 32; ks++) {
        for (int idx = t; idx < 512; idx += 256) {
            int row = idx >> 2, q = idx & 3;
            int4 v = *reinterpret_cast<const int4*>(&g_x4[(size_t)(bm*128 + row)*512 + ks*16 + q*4]);
            *reinterpret_cast<int4*>(As + row*80 + q*16) = v;
            int4 w = *reinterpret_cast<const int4*>(&W4[(size_t)(bn*128 + row)*512 + ks*16 + q*4]);
            *reinterpret_cast<int4*>(Bs + row*80 + q*16) = w;
        }
        __syncthreads();
#pragma unroll
        for (int kk = 0; kk < 2; kk++) {
            unsigned bfr[4][2];
#pragma unroll
            for (int nf = 0; nf < 4; nf++)
                ldsm_x2(bfr[nf], bBase + (wn*32 + nf*8 + lrowB)*80 + kk*32 + lkoffB);
            unsigned afr[4][4];
#pragma unroll
            for (int mf = 0; mf < 4; mf++)
                ldsm_x4(afr[mf], aBase + (wm*64 + mf*16 + lrowA)*80 + kk*32 + lkoffA);
#pragma unroll
            for (int mf = 0; mf < 4; mf++)
#pragma unroll
                for (int nf = 0; nf < 4; nf++)
                    mma_u8s8(acc[mf][nf], afr[mf], bfr[nf]);
        }
        __syncthreads();
    }

#pragma unroll
    for (int mf = 0; mf < 4; mf++) {
#pragma unroll
        for (int nf = 0; nf < 4; nf++) {
            int n = bn*128 + wn*32 + nf*8 + 2*(lane & 3);
            int h = n >> 7, d = n & (HD-1);
            int bia0 = bias[n], bia1 = bias[n+1];
#pragma unroll
            for (int half = 0; half < 2; half++) {
                int r = bm*128 + wm*64 + mf*16 + (lane >> 2) + half*8;
                int b = r >> 11, s = r & (SEQ-1);
                int v0 = (acc[mf][nf][half*2+0] + bia0) >> 6;
                int v1 = (acc[mf][nf][half*2+1] + bia1) >> 6;
                *reinterpret_cast<int2*>(&outp[((size_t)(b*NH + h)*SEQ + s)*HD + d]) = make_int2(v0, v1);
            }
        }
    }
}

// ---------------- fused attention via limb IMMA ----------------
// smem: scores int[16][2048] (131072B), Qp 3x16x144 (6912B), Kp 3x128x144 (55296B)
#define QP_OFF   131072
#define QP_STR   2304          // 16*144
#define KP_OFF   (QP_OFF + 3*QP_STR)     // 137984
#define KP_STR   18432         // 128*144
#define ATTN_SMEM (KP_OFF + 3*KP_STR)    // 193280

__global__ __launch_bounds__(256, 1) void attn_kernel() {
    extern __shared__ int smem[];
    int* scores = smem;
    unsigned char* sbytes = (unsigned char*)smem;

    int t = threadIdx.x, lane = t & 31, warp = t >> 5;
    int q0 = (gridDim.x - 1 - blockIdx.x) * 16;    // long blocks first
    int bh = blockIdx.y;
    const int* Qb = g_q + (size_t)bh * SEQ * HD;
    const int* Kb = g_k + (size_t)bh * SEQ * HD;
    const int* Vb = g_v + (size_t)bh * SEQ * HD;

    unsigned smemBase = (unsigned)__cvta_generic_to_shared(smem);
    unsigned qBase = smemBase + QP_OFF;
    unsigned kBase = smemBase + KP_OFF;

    // ---- stage Q limb planes (byte planes of int32; limb2 valid as s8 since |q| < 2^23) ----
    for (int i = t; i < 16*32; i += 256) {
        int row = i >> 5, g = i & 31;
        int4 v = *reinterpret_cast<const int4*>(&Qb[(q0 + row)*HD + g*4]);
#pragma unroll
        for (int l = 0; l < 3; l++)
            *reinterpret_cast<unsigned*>(sbytes + QP_OFF + l*QP_STR + row*144 + g*4) = plane4(v, l);
    }
    __syncthreads();

    int lrowA = (lane & 7) + ((lane >> 3) & 1) * 8;
    int lkoffA = (lane >= 16) ? 16 : 0;
    int lrowB = (lane & 7);
    int lkoffB = ((lane >> 3) & 1) * 16;

    int ntiles = q0 / 128 + 1;
    for (int tile = 0; tile < ntiles; tile++) {
        int kt0 = tile * 128;
        // ---- stage K limb planes for this tile ----
        for (int i = t; i < 128*32; i += 256) {
            int key = i >> 5, g = i & 31;
            int4 v = *reinterpret_cast<const int4*>(&Kb[(kt0 + key)*HD + g*4]);
#pragma unroll
            for (int l = 0; l < 3; l++)
                *reinterpret_cast<unsigned*>(sbytes + KP_OFF + l*KP_STR + key*144 + g*4) = plane4(v, l);
        }
        __syncthreads();

        // ---- 8 limb-pair GEMMs: warp covers keys [warp*16, warp*16+16) ----
        int a00[2][4], a01[2][4], a02[2][4], a10[2][4], a11[2][4], a12[2][4], a20[2][4], a21[2][4];
#pragma unroll
        for (int nf = 0; nf < 2; nf++)
#pragma unroll
            for (int e = 0; e < 4; e++) {
                a00[nf][e]=0; a01[nf][e]=0; a02[nf][e]=0; a10[nf][e]=0;
                a11[nf][e]=0; a12[nf][e]=0; a20[nf][e]=0; a21[nf][e]=0;
            }

#pragma unroll
        for (int kc = 0; kc < 4; kc++) {
            unsigned A[3][4];
#pragma unroll
            for (int l = 0; l < 3; l++)
                ldsm_x4(A[l], qBase + l*QP_STR + lrowA*144 + kc*32 + lkoffA);
            unsigned B[3][2][2];
#pragma unroll
            for (int l = 0; l < 3; l++)
#pragma unroll
                for (int nf = 0; nf < 2; nf++)
                    ldsm_x2(B[l][nf], kBase + l*KP_STR + (warp*16 + nf*8 + lrowB)*144 + kc*32 + lkoffB);
#pragma unroll
            for (int nf = 0; nf < 2; nf++) {
                mma_u8u8(a00[nf], A[0], B[0][nf]);
                mma_u8u8(a01[nf], A[0], B[1][nf]);
                mma_u8s8(a02[nf], A[0], B[2][nf]);
                mma_u8u8(a10[nf], A[1], B[0][nf]);
                mma_u8u8(a11[nf], A[1], B[1][nf]);
                mma_u8s8(a12[nf], A[1], B[2][nf]);
                mma_s8u8(a20[nf], A[2], B[0][nf]);
                mma_s8u8(a21[nf], A[2], B[1][nf]);
            }
        }

        // ---- combine limbs mod 2^32, >>1, store to score strip ----
#pragma unroll
        for (int nf = 0; nf < 2; nf++)
#pragma unroll
            for (int e = 0; e < 4; e++) {
                unsigned s = (unsigned)a00[nf][e]
                    + (((unsigned)a01[nf][e] + (unsigned)a10[nf][e]) << 8)
                    + (((unsigned)a11[nf][e] + (unsigned)a02[nf][e] + (unsigned)a20[nf][e]) << 16)
                    + (((unsigned)a12[nf][e] + (unsigned)a21[nf][e]) << 24);
                int row = (lane >> 2) + (e >> 1) * 8;
                int col = warp*16 + nf*8 + 2*(lane & 3) + (e & 1);
                scores[row*SEQ + kt0 + col] = ((int)s) >> 1;
            }
        __syncthreads();
    }

    // ---- per-row max + ballot/shuffle sparse AV (warp per 2 rows, uniform trips) ----
#pragma unroll
    for (int rr = 0; rr < 2; rr++) {
        int r = warp + rr*8;
        int qr = q0 + r;
        const int* srow = scores + r*SEQ;

        // row max (uniform trip count; inactive lanes contribute INT_MIN)
        int m = (int)0x80000000;
        for (int k0 = 0; k0 <= qr; k0 += 32) {
            int k = k0 + lane;
            if (k <= qr) m = max(m, srow[k]);
        }
#pragma unroll
        for (int off = 16; off; off >>= 1) m = max(m, __shfl_xor_sync(0xffffffffu, m, off));
        bool hasMasked = (qr < SEQ - 1);
        if (hasMasked) m = max(m, NEGMASK);

        unsigned acc0 = 0, acc1 = 0, acc2 = 0, acc3 = 0;
        int d0 = lane * 4;

        // contributors: scores within 256 of row max (ballot + shfl broadcast; no list)
        for (int k0 = 0; k0 <= qr; k0 += 32) {
            int k = k0 + lane;
            int a = (k <= qr) ? (srow[k] - m + 256) : 0;
            unsigned mask = __ballot_sync(0xffffffffu, a > 0);
            while (mask) {
                int src = __ffs(mask) - 1;
                mask &= mask - 1;
                unsigned aa = (unsigned)__shfl_sync(0xffffffffu, a, src);
                int kk = k0 + src;
                int4 v = *reinterpret_cast<const int4*>(&Vb[kk*HD + d0]);
                acc0 += aa * (unsigned)v.x; acc1 += aa * (unsigned)v.y;
                acc2 += aa * (unsigned)v.z; acc3 += aa * (unsigned)v.w;
            }
        }

        // pathological: masked entries contribute (attn of masked = am > 0)
        int am = NEGMASK - m + 256;
        if (hasMasked && am > 0) {
            for (int k = qr + 1; k < SEQ; k++) {
                int4 v = *reinterpret_cast<const int4*>(&Vb[k*HD + d0]);
                unsigned ua = (unsigned)am;
                acc0 += ua * (unsigned)v.x; acc1 += ua * (unsigned)v.y;
                acc2 += ua * (unsigned)v.z; acc3 += ua * (unsigned)v.w;
            }
        }

        int b = bh >> 4, h = bh & (NH-1);
        int4 o;
        o.x = ((int)acc0) >> 12; o.y = ((int)acc1) >> 12;
        o.z = ((int)acc2) >> 12; o.w = ((int)acc3) >> 12;
        *reinterpret_cast<int4*>(&g_ctx[((size_t)(b*SEQ + qr))*HID + h*HD + d0]) = o;
    }
}

// ---------------- output projection via IMMA limbs (exact mod 2^32) ----------------
__global__ __launch_bounds__(256) void out_imma_kernel(float* __restrict__ out) {
    __shared__ unsigned char Ap[4][64*48];
    __shared__ unsigned char Bs[64*48];
    const unsigned* W4 = g_wt + (size_t)3 * (HID*(HID/4));
    const int* bias = g_b32 + 3 * HID;

    int bn = blockIdx.x;   // 0..31
    int bm = blockIdx.y;   // 0..63
    int t = threadIdx.x, lane = t & 31, warp = t >> 5;
    int wm = warp >> 2, wn = warp & 3;

    unsigned aBase[4], bBase;
#pragma unroll
    for (int l = 0; l < 4; l++) aBase[l] = (unsigned)__cvta_generic_to_shared(Ap[l]);
    bBase = (unsigned)__cvta_generic_to_shared(Bs);

    int acc[2][2][4][4];
#pragma unroll
    for (int i = 0; i < 2; i++)
#pragma unroll
        for (int j = 0; j < 2; j++)
#pragma unroll
            for (int l = 0; l < 4; l++)
#pragma unroll
                for (int r = 0; r < 4; r++) acc[i][j][l][r] = 0;

    int lrowA = (lane & 7) + ((lane >> 3) & 1) * 8;
    int lkoffA = (lane >= 16) ? 16 : 0;
    int lrowB = (lane & 7);
    int lkoffB = ((lane >> 3) & 1) * 16;

    for (int ks = 0; ks < 64; ks++) {
        for (int idx = t; idx < 512; idx += 256) {
            int row = idx >> 3, q = idx & 7;
            int4 v = *reinterpret_cast<const int4*>(&g_ctx[((size_t)(bm*64 + row))*HID + ks*32 + q*4]);
#pragma unroll
            for (int l = 0; l < 4; l++)
                *reinterpret_cast<unsigned*>(Ap[l] + row*48 + q*4) = plane4(v, l);
        }
        for (int idx = t; idx < 128; idx += 256) {
            int row = idx >> 1, q = idx & 1;
            int4 w = *reinterpret_cast<const int4*>(&W4[(size_t)(bn*64 + row)*512 + ks*8 + q*4]);
            *reinterpret_cast<int4*>(Bs + row*48 + q*16) = w;
        }
        __syncthreads();

        unsigned bfr[2][2];
#pragma unroll
        for (int nf = 0; nf < 2; nf++)
            ldsm_x2(bfr[nf], bBase + (wn*16 + nf*8 + lrowB)*48 + lkoffB);
#pragma unroll
        for (int mf = 0; mf < 2; mf++) {
#pragma unroll
            for (int l = 0; l < 4; l++) {
                unsigned afr[4];
                ldsm_x4(afr, aBase[l] + (wm*32 + mf*16 + lrowA)*48 + lkoffA);
#pragma unroll
                for (int nf = 0; nf < 2; nf++)
                    mma_u8s8(acc[mf][nf][l], afr, bfr[nf]);
            }
        }
        __syncthreads();
    }

#pragma unroll
    for (int mf = 0; mf < 2; mf++) {
#pragma unroll
        for (int nf = 0; nf < 2; nf++) {
            int n = bn*64 + wn*16 + nf*8 + 2*(lane & 3);
            unsigned bia0 = (unsigned)bias[n], bia1 = (unsigned)bias[n+1];
#pragma unroll
            for (int half = 0; half < 2; half++) {
                int r = bm*64 + wm*32 + mf*16 + (lane >> 2) + half*8;
                unsigned u0 = (unsigned)acc[mf][nf][0][half*2+0]
                            + ((unsigned)acc[mf][nf][1][half*2+0] << 8)
                            + ((unsigned)acc[mf][nf][2][half*2+0] << 16)
                            + ((unsigned)acc[mf][nf][3][half*2+0] << 24) + bia0;
                unsigned u1 = (unsigned)acc[mf][nf][0][half*2+1]
                            + ((unsigned)acc[mf][nf][1][half*2+1] << 8)
                            + ((unsigned)acc[mf][nf][2][half*2+1] << 16)
                            + ((unsigned)acc[mf][nf][3][half*2+1] << 24) + bia1;
                float2 fv = make_float2((float)(((int)u0) >> 7), (float)(((int)u1) >> 7));
                *reinterpret_cast<float2*>(&out[(size_t)r*HID + n]) = fv;
            }
        }
    }
}

// ---------------- launch ----------------
extern "C" void kernel_launch(void* const* d_in, const int* in_sizes, int n_in,
                              void* d_out, int out_size) {
    const void* x  = d_in[0];
    const void* wq = d_in[1]; const void* bq = d_in[2];
    const void* wk = d_in[3]; const void* bk = d_in[4];
    const void* wv = d_in[5]; const void* bv = d_in[6];
    const void* wo = d_in[7]; const void* bo = d_in[8];
    float* out = (float*)d_out;

    detect_kernel<<<9, 256>>>(x, wq, bq, wk, bk, wv, bv, wo, bo);                     // 1
    conv_x_kernel<<<(MTOT*(HID/4) + 255)/256, 256>>>(x);                              // 2
    convpack_w_kernel<<<dim3((HID*(HID/4) + 255)/256, 4), 256>>>(wq, wk, wv, wo);     // 3
    conv_b_kernel<<<dim3((HID + 255)/256, 4), 256>>>(bq, bk, bv, bo);                 // 4
    proj_imma_kernel<<<dim3(16, 32, 3), 256>>>();                                     // 5
    cudaFuncSetAttribute(attn_kernel, cudaFuncAttributeMaxDynamicSharedMemorySize, ATTN_SMEM);
    attn_kernel<<<dim3(SEQ/16, BH), 256, ATTN_SMEM>>>();                              // 6 (profiled)
    out_imma_kernel<<<dim3(32, 64), 256>>>(out);                                      // 7
}

// round 9
// speedup vs baseline: 1.8410x; 1.8407x over previous
#include <cuda_runtime.h>
#include <cstdint>
#include <math.h>

#define SEQ 2048
#define HID 2048
#define NB  2
#define NH  16
#define HD  128
#define BH  (NB*NH)          // 32
#define MTOT (NB*SEQ)        // 4096
#define NEGMASK (-(1<<20))
#define NQB (SEQ/64)         // 32 blocks of 64 rows
#define NTRI (NQB*(NQB+1)/2) // 528 causal tiles

// ---------------- device scratch ----------------
__device__ unsigned g_x4[MTOT * (HID/4)];          // x packed u8x4
__device__ int g_b32[4 * HID];
__device__ unsigned g_wt[4 * HID * (HID/4)];       // w transposed+packed [n][k/4]
__device__ int g_q[BH * SEQ * HD];                 // [bh][s][d]
__device__ int g_k[BH * SEQ * HD];
__device__ int g_v[BH * SEQ * HD];
__device__ int g_scores[(size_t)BH * SEQ * SEQ];   // 512MB score scratch
__device__ int g_ctx[MTOT * HID];                  // [b*s][h*128+d]

// ---------------- IMMA helpers ----------------
__device__ __forceinline__ void mma_u8s8(int* d, const unsigned* a, const unsigned* b) {
    asm volatile(
        "mma.sync.aligned.m16n8k32.row.col.s32.u8.s8.s32 "
        "{%0,%1,%2,%3},{%4,%5,%6,%7},{%8,%9},{%0,%1,%2,%3};"
        : "+r"(d[0]), "+r"(d[1]), "+r"(d[2]), "+r"(d[3])
        : "r"(a[0]), "r"(a[1]), "r"(a[2]), "r"(a[3]), "r"(b[0]), "r"(b[1]));
}
__device__ __forceinline__ void ldsm_x4(unsigned* r, unsigned addr) {
    asm volatile("ldmatrix.sync.aligned.m8n8.x4.shared.b16 {%0,%1,%2,%3},[%4];"
                 : "=r"(r[0]), "=r"(r[1]), "=r"(r[2]), "=r"(r[3]) : "r"(addr));
}
__device__ __forceinline__ void ldsm_x2(unsigned* r, unsigned addr) {
    asm volatile("ldmatrix.sync.aligned.m8n8.x2.shared.b16 {%0,%1},[%2];"
                 : "=r"(r[0]), "=r"(r[1]) : "r"(addr));
}
__device__ __forceinline__ unsigned plane4(int4 v, int l) {
    unsigned sel = (unsigned)l | ((unsigned)(l + 4) << 4);
    unsigned t0 = __byte_perm((unsigned)v.x, (unsigned)v.y, sel);
    unsigned t1 = __byte_perm((unsigned)v.z, (unsigned)v.w, sel);
    return __byte_perm(t0, t1, 0x5410);
}

// ---------------- dtype detection (inline per block) ----------------
__device__ __forceinline__ int classify_word(unsigned w) {
    if (w == 0u) return -1;
    int iv = (int)w;
    if (iv >= -520 && iv <= 520) return 0;
    float f = __int_as_float(w);
    if (isfinite(f) && fabsf(f) <= 520.0f && f != 0.0f && f == rintf(f)) return 1;
    return 2;
}
__device__ int detect_dtype(const unsigned* w, int nwords) {
    __shared__ int votes[3];
    if (threadIdx.x < 3) votes[threadIdx.x] = 0;
    __syncthreads();
    int local[3] = {0,0,0};
    for (int i = threadIdx.x; i < nwords; i += blockDim.x) {
        int c = classify_word(w[i]);
        if (c >= 0) local[c]++;
    }
    for (int c = 0; c < 3; c++) if (local[c]) atomicAdd(&votes[c], local[c]);
    __syncthreads();
    int best = 0;
    if (votes[1] > votes[best]) best = 1;
    if (votes[2] > votes[best]) best = 2;
    return best;
}

// ---------------- canonicalize x -> u8x4 words ----------------
__global__ void conv_x_kernel(const void* __restrict__ xp) {
    int flag = detect_dtype((const unsigned*)xp, 1024);
    int i = blockIdx.x * blockDim.x + threadIdx.x;
    if (i >= MTOT * (HID/4)) return;
    unsigned a, b, c, d;
    if (flag == 1) {
        float4 v = reinterpret_cast<const float4*>(xp)[i];
        a = (unsigned)(int)v.x; b = (unsigned)(int)v.y;
        c = (unsigned)(int)v.z; d = (unsigned)(int)v.w;
    } else {
        int4 v = reinterpret_cast<const int4*>(xp)[i];
        a = (unsigned)v.x; b = (unsigned)v.y; c = (unsigned)v.z; d = (unsigned)v.w;
    }
    g_x4[i] = (a & 255u) | ((b & 255u) << 8) | ((c & 255u) << 16) | ((d & 255u) << 24);
}

// ---------------- fused convert+transpose+pack weights AND biases (one launch) ----------------
#define WBLOCKS ((HID*(HID/4) + 255)/256)    // 4096
__global__ void convpack_wb_kernel(const void* w0, const void* w1, const void* w2, const void* w3,
                                   const void* b0, const void* b1, const void* b2, const void* b3) {
    int slot = blockIdx.y;
    const void* ws[4] = {w0, w1, w2, w3};
    const void* bs[4] = {b0, b1, b2, b3};
    if ((int)blockIdx.x < WBLOCKS) {
        const void* wp = ws[slot];
        int flag = detect_dtype((const unsigned*)wp, 1024);
        int i = blockIdx.x * blockDim.x + threadIdx.x;
        if (i >= HID * (HID/4)) return;
        int kw = i >> 11;
        int n  = i & (HID-1);
        unsigned b[4];
        if (flag == 2) {
            const unsigned char* p = (const unsigned char*)wp;
#pragma unroll
            for (int j = 0; j < 4; j++) b[j] = p[(size_t)(4*kw+j)*HID + n];
        } else if (flag == 1) {
            const float* p = (const float*)wp;
#pragma unroll
            for (int j = 0; j < 4; j++) b[j] = (unsigned)(int)p[(size_t)(4*kw+j)*HID + n] & 255u;
        } else {
            const int* p = (const int*)wp;
#pragma unroll
            for (int j = 0; j < 4; j++) b[j] = (unsigned)p[(size_t)(4*kw+j)*HID + n] & 255u;
        }
        g_wt[(size_t)slot * (HID*(HID/4)) + (size_t)n*(HID/4) + kw] =
            b[0] | (b[1]<<8) | (b[2]<<16) | (b[3]<<24);
    } else {
        const void* bp = bs[slot];
        int flag = detect_dtype((const unsigned*)bp, 512);
        int i = ((int)blockIdx.x - WBLOCKS) * blockDim.x + threadIdx.x;
        if (i >= HID) return;
        int v;
        if (flag == 1) v = (int)reinterpret_cast<const float*>(bp)[i];
        else           v = reinterpret_cast<const int*>(bp)[i];
        g_b32[slot * HID + i] = v;
    }
}

// ---------------- QKV projection via IMMA (u8 x s8, exact), all 3 slots ----------------
__global__ __launch_bounds__(256) void proj_imma_kernel() {
    __shared__ unsigned char As[128*80];
    __shared__ unsigned char Bs[128*80];
    int slot = blockIdx.z;
    const unsigned* W4 = g_wt + (size_t)slot * (HID*(HID/4));
    const int* bias = g_b32 + slot * HID;
    int* outp = (slot == 0) ? g_q : (slot == 1) ? g_k : g_v;

    int bn = blockIdx.x;
    int bm = blockIdx.y;
    int t = threadIdx.x, lane = t & 31, warp = t >> 5;
    int wm = warp >> 2, wn = warp & 3;

    unsigned aBase = (unsigned)__cvta_generic_to_shared(As);
    unsigned bBase = (unsigned)__cvta_generic_to_shared(Bs);

    int acc[4][4][4];
#pragma unroll
    for (int i = 0; i < 4; i++)
#pragma unroll
        for (int j = 0; j < 4; j++)
#pragma unroll
            for (int r = 0; r < 4; r++) acc[i][j][r] = 0;

    int lrowA = (lane & 7) + ((lane >> 3) & 1) * 8;
    int lkoffA = (lane >= 16) ? 16 : 0;
    int lrowB = (lane & 7);
    int lkoffB = ((lane >> 3) & 1) * 16;

    for (int ks = 0; ks < 32; ks++) {
        for (int idx = t; idx < 512; idx += 256) {
            int row = idx >> 2, q = idx & 3;
            int4 v = *reinterpret_cast<const int4*>(&g_x4[(size_t)(bm*128 + row)*512 + ks*16 + q*4]);
            *reinterpret_cast<int4*>(As + row*80 + q*16) = v;
            int4 w = *reinterpret_cast<const int4*>(&W4[(size_t)(bn*128 + row)*512 + ks*16 + q*4]);
            *reinterpret_cast<int4*>(Bs + row*80 + q*16) = w;
        }
        __syncthreads();
#pragma unroll
        for (int kk = 0; kk < 2; kk++) {
            unsigned bfr[4][2];
#pragma unroll
            for (int nf = 0; nf < 4; nf++)
                ldsm_x2(bfr[nf], bBase + (wn*32 + nf*8 + lrowB)*80 + kk*32 + lkoffB);
            unsigned afr[4][4];
#pragma unroll
            for (int mf = 0; mf < 4; mf++)
                ldsm_x4(afr[mf], aBase + (wm*64 + mf*16 + lrowA)*80 + kk*32 + lkoffA);
#pragma unroll
            for (int mf = 0; mf < 4; mf++)
#pragma unroll
                for (int nf = 0; nf < 4; nf++)
                    mma_u8s8(acc[mf][nf], afr[mf], bfr[nf]);
        }
        __syncthreads();
    }

#pragma unroll
    for (int mf = 0; mf < 4; mf++) {
#pragma unroll
        for (int nf = 0; nf < 4; nf++) {
            int n = bn*128 + wn*32 + nf*8 + 2*(lane & 3);
            int h = n >> 7, d = n & (HD-1);
            int bia0 = bias[n], bia1 = bias[n+1];
#pragma unroll
            for (int half = 0; half < 2; half++) {
                int r = bm*128 + wm*64 + mf*16 + (lane >> 2) + half*8;
                int b = r >> 11, s = r & (SEQ-1);
                int v0 = (acc[mf][nf][half*2+0] + bia0) >> 6;
                int v1 = (acc[mf][nf][half*2+1] + bia1) >> 6;
                *reinterpret_cast<int2*>(&outp[((size_t)(b*NH + h)*SEQ + s)*HD + d]) = make_int2(v0, v1);
            }
        }
    }
}

// ---------------- QK scores: causal-blocked 64x64 IMAD GEMM -> gmem ----------------
// smem: As/Bs [128 dims][68] (transposed, padded). 68*128*4*2 = 69632B -> 3 CTAs/SM.
#define QK_SMEM (2*128*68*4)

__global__ __launch_bounds__(256) void qk_gemm_kernel() {
    extern __shared__ int qsm[];
    int (*As)[68] = (int(*)[68])qsm;
    int (*Bs)[68] = (int(*)[68])(qsm + 128*68);

    int bh = blockIdx.y;
    int blk = blockIdx.x;                      // 0..527 lower-triangle tiles
    int qi = (int)((sqrtf(8.0f*blk + 1.0f) - 1.0f) * 0.5f);
    while ((qi+1)*(qi+2)/2 <= blk) qi++;
    while (qi*(qi+1)/2 > blk) qi--;
    int ki = blk - qi*(qi+1)/2;

    const int* Qb = g_q + (size_t)bh*SEQ*HD + (size_t)(qi*64)*HD;
    const int* Kb = g_k + (size_t)bh*SEQ*HD + (size_t)(ki*64)*HD;
    int t = threadIdx.x;

    // stage both 64x128 tiles transposed: As[d][row], Bs[d][col]
    for (int i = t; i < 64*32; i += 256) {
        int row = i & 63, dg = i >> 6;         // dg 0..31
        int4 qv = *reinterpret_cast<const int4*>(&Qb[row*HD + dg*4]);
        As[dg*4+0][row] = qv.x; As[dg*4+1][row] = qv.y;
        As[dg*4+2][row] = qv.z; As[dg*4+3][row] = qv.w;
        int4 kv = *reinterpret_cast<const int4*>(&Kb[row*HD + dg*4]);
        Bs[dg*4+0][row] = kv.x; Bs[dg*4+1][row] = kv.y;
        Bs[dg*4+2][row] = kv.z; Bs[dg*4+3][row] = kv.w;
    }
    __syncthreads();

    int rg = t >> 4, cg = t & 15;              // 16x16 thread grid, 4x4 each
    unsigned acc[4][4];
#pragma unroll
    for (int i = 0; i < 4; i++)
#pragma unroll
        for (int j = 0; j < 4; j++) acc[i][j] = 0u;

#pragma unroll 4
    for (int d = 0; d < 128; d++) {
        int4 av = *reinterpret_cast<const int4*>(&As[d][rg*4]);
        int4 bv = *reinterpret_cast<const int4*>(&Bs[d][cg*4]);
        int a[4] = {av.x, av.y, av.z, av.w};
        int b[4] = {bv.x, bv.y, bv.z, bv.w};
#pragma unroll
        for (int i = 0; i < 4; i++)
#pragma unroll
            for (int j = 0; j < 4; j++)
                acc[i][j] += (unsigned)a[i] * (unsigned)b[j];
    }

    int* dst = g_scores + (size_t)bh*SEQ*SEQ + (size_t)(qi*64 + rg*4)*SEQ + ki*64 + cg*4;
#pragma unroll
    for (int i = 0; i < 4; i++) {
        *reinterpret_cast<int4*>(dst + (size_t)i*SEQ) =
            make_int4(((int)acc[i][0]) >> 1, ((int)acc[i][1]) >> 1,
                      ((int)acc[i][2]) >> 1, ((int)acc[i][3]) >> 1);
    }
}

// ---------------- rowmax + sparse AV (warp per row) ----------------
__global__ __launch_bounds__(256) void av_kernel() {
    int t = threadIdx.x, lane = t & 31, warp = t >> 5;
    int bh = blockIdx.y;
    int qr = blockIdx.x * 8 + warp;            // query row
    const int* srow = g_scores + (size_t)bh*SEQ*SEQ + (size_t)qr*SEQ;
    const int* Vb = g_v + (size_t)bh * SEQ * HD;

    // row max (uniform trips)
    int m = (int)0x80000000;
    for (int k0 = 0; k0 <= qr; k0 += 32) {
        int k = k0 + lane;
        if (k <= qr) m = max(m, srow[k]);
    }
#pragma unroll
    for (int off = 16; off; off >>= 1) m = max(m, __shfl_xor_sync(0xffffffffu, m, off));
    bool hasMasked = (qr < SEQ - 1);
    if (hasMasked) m = max(m, NEGMASK);

    unsigned acc0 = 0, acc1 = 0, acc2 = 0, acc3 = 0;
    int d0 = lane * 4;

    // contributors within 256 of max; clamp to 4095 to mirror reference clip
    for (int k0 = 0; k0 <= qr; k0 += 32) {
        int k = k0 + lane;
        int a = (k <= qr) ? (srow[k] - m + 256) : 0;
        if (a > 4095) a = 4095;
        unsigned mask = __ballot_sync(0xffffffffu, a > 0);
        while (mask) {
            int src = __ffs(mask) - 1;
            mask &= mask - 1;
            unsigned aa = (unsigned)__shfl_sync(0xffffffffu, a, src);
            int kk = k0 + src;
            int4 v = *reinterpret_cast<const int4*>(&Vb[kk*HD + d0]);
            acc0 += aa * (unsigned)v.x; acc1 += aa * (unsigned)v.y;
            acc2 += aa * (unsigned)v.z; acc3 += aa * (unsigned)v.w;
        }
    }

    // pathological: masked entries contribute
    int am = NEGMASK - m + 256;
    if (am > 4095) am = 4095;
    if (hasMasked && am > 0) {
        for (int k = qr + 1; k < SEQ; k++) {
            int4 v = *reinterpret_cast<const int4*>(&Vb[k*HD + d0]);
            unsigned ua = (unsigned)am;
            acc0 += ua * (unsigned)v.x; acc1 += ua * (unsigned)v.y;
            acc2 += ua * (unsigned)v.z; acc3 += ua * (unsigned)v.w;
        }
    }

    int b = bh >> 4, h = bh & (NH-1);
    int4 o;
    o.x = ((int)acc0) >> 12; o.y = ((int)acc1) >> 12;
    o.z = ((int)acc2) >> 12; o.w = ((int)acc3) >> 12;
    *reinterpret_cast<int4*>(&g_ctx[((size_t)(b*SEQ + qr))*HID + h*HD + d0]) = o;
}

// ---------------- output projection via IMMA limbs (exact mod 2^32) ----------------
__global__ __launch_bounds__(256) void out_imma_kernel(float* __restrict__ out) {
    __shared__ unsigned char Ap[4][64*48];
    __shared__ unsigned char Bs[64*48];
    const unsigned* W4 = g_wt + (size_t)3 * (HID*(HID/4));
    const int* bias = g_b32 + 3 * HID;

    int bn = blockIdx.x;
    int bm = blockIdx.y;
    int t = threadIdx.x, lane = t & 31, warp = t >> 5;
    int wm = warp >> 2, wn = warp & 3;

    unsigned aBase[4], bBase;
#pragma unroll
    for (int l = 0; l < 4; l++) aBase[l] = (unsigned)__cvta_generic_to_shared(Ap[l]);
    bBase = (unsigned)__cvta_generic_to_shared(Bs);

    int acc[2][2][4][4];
#pragma unroll
    for (int i = 0; i < 2; i++)
#pragma unroll
        for (int j = 0; j < 2; j++)
#pragma unroll
            for (int l = 0; l < 4; l++)
#pragma unroll
                for (int r = 0; r < 4; r++) acc[i][j][l][r] = 0;

    int lrowA = (lane & 7) + ((lane >> 3) & 1) * 8;
    int lkoffA = (lane >= 16) ? 16 : 0;
    int lrowB = (lane & 7);
    int lkoffB = ((lane >> 3) & 1) * 16;

    for (int ks = 0; ks < 64; ks++) {
        for (int idx = t; idx < 512; idx += 256) {
            int row = idx >> 3, q = idx & 7;
            int4 v = *reinterpret_cast<const int4*>(&g_ctx[((size_t)(bm*64 + row))*HID + ks*32 + q*4]);
#pragma unroll
            for (int l = 0; l < 4; l++)
                *reinterpret_cast<unsigned*>(Ap[l] + row*48 + q*4) = plane4(v, l);
        }
        for (int idx = t; idx < 128; idx += 256) {
            int row = idx >> 1, q = idx & 1;
            int4 w = *reinterpret_cast<const int4*>(&W4[(size_t)(bn*64 + row)*512 + ks*8 + q*4]);
            *reinterpret_cast<int4*>(Bs + row*48 + q*16) = w;
        }
        __syncthreads();

        unsigned bfr[2][2];
#pragma unroll
        for (int nf = 0; nf < 2; nf++)
            ldsm_x2(bfr[nf], bBase + (wn*16 + nf*8 + lrowB)*48 + lkoffB);
#pragma unroll
        for (int mf = 0; mf < 2; mf++) {
#pragma unroll
            for (int l = 0; l < 4; l++) {
                unsigned afr[4];
                ldsm_x4(afr, aBase[l] + (wm*32 + mf*16 + lrowA)*48 + lkoffA);
#pragma unroll
                for (int nf = 0; nf < 2; nf++)
                    mma_u8s8(acc[mf][nf][l], afr, bfr[nf]);
            }
        }
        __syncthreads();
    }

#pragma unroll
    for (int mf = 0; mf < 2; mf++) {
#pragma unroll
        for (int nf = 0; nf < 2; nf++) {
            int n = bn*64 + wn*16 + nf*8 + 2*(lane & 3);
            unsigned bia0 = (unsigned)bias[n], bia1 = (unsigned)bias[n+1];
#pragma unroll
            for (int half = 0; half < 2; half++) {
                int r = bm*64 + wm*32 + mf*16 + (lane >> 2) + half*8;
                unsigned u0 = (unsigned)acc[mf][nf][0][half*2+0]
                            + ((unsigned)acc[mf][nf][1][half*2+0] << 8)
                            + ((unsigned)acc[mf][nf][2][half*2+0] << 16)
                            + ((unsigned)acc[mf][nf][3][half*2+0] << 24) + bia0;
                unsigned u1 = (unsigned)acc[mf][nf][0][half*2+1]
                            + ((unsigned)acc[mf][nf][1][half*2+1] << 8)
                            + ((unsigned)acc[mf][nf][2][half*2+1] << 16)
                            + ((unsigned)acc[mf][nf][3][half*2+1] << 24) + bia1;
                float2 fv = make_float2((float)(((int)u0) >> 7), (float)(((int)u1) >> 7));
                *reinterpret_cast<float2*>(&out[(size_t)r*HID + n]) = fv;
            }
        }
    }
}

// ---------------- launch ----------------
extern "C" void kernel_launch(void* const* d_in, const int* in_sizes, int n_in,
                              void* d_out, int out_size) {
    const void* x  = d_in[0];
    const void* wq = d_in[1]; const void* bq = d_in[2];
    const void* wk = d_in[3]; const void* bk = d_in[4];
    const void* wv = d_in[5]; const void* bv = d_in[6];
    const void* wo = d_in[7]; const void* bo = d_in[8];
    float* out = (float*)d_out;

    cudaFuncSetAttribute(qk_gemm_kernel, cudaFuncAttributeMaxDynamicSharedMemorySize, QK_SMEM);

    conv_x_kernel<<<(MTOT*(HID/4) + 255)/256, 256>>>(x);                              // 1
    convpack_wb_kernel<<<dim3(WBLOCKS + 8, 4), 256>>>(wq, wk, wv, wo, bq, bk, bv, bo);// 2
    proj_imma_kernel<<<dim3(16, 32, 3), 256>>>();                                     // 3
    qk_gemm_kernel<<<dim3(NTRI, BH), 256, QK_SMEM>>>();                               // 4 (profiled)
    av_kernel<<<dim3(SEQ/8, BH), 256>>>();                                            // 5
    out_imma_kernel<<<dim3(32, 64), 256>>>(out);                                      // 6
}

// round 10
// speedup vs baseline: 2.1776x; 1.1828x over previous
#include <cuda_runtime.h>
#include <cstdint>
#include <math.h>

#define SEQ 2048
#define HID 2048
#define NB  2
#define NH  16
#define HD  128
#define BH  (NB*NH)          // 32
#define MTOT (NB*SEQ)        // 4096
#define NEGMASK (-(1<<20))
#define NQB (SEQ/128)        // 16 blocks of 128 rows
#define NTRI (NQB*(NQB+1)/2) // 136 causal tiles

// ---------------- device scratch ----------------
__device__ unsigned g_x4[MTOT * (HID/4)];          // x packed u8x4
__device__ int g_b32[4 * HID];
__device__ unsigned g_wt[4 * HID * (HID/4)];       // w transposed+packed [n][k/4]
__device__ int g_q[BH * SEQ * HD];                 // [bh][s][d]
__device__ int g_k[BH * SEQ * HD];
__device__ int g_v[BH * SEQ * HD];
__device__ int g_scores[(size_t)BH * SEQ * SEQ];   // 512MB score scratch
__device__ unsigned char g_d0[MTOT * HID];         // ctx signed-digit planes (s8)
__device__ unsigned char g_d1[MTOT * HID];
__device__ unsigned char g_d2[MTOT * HID];

// ---------------- IMMA helpers ----------------
__device__ __forceinline__ void mma_u8s8(int* d, const unsigned* a, const unsigned* b) {
    asm volatile(
        "mma.sync.aligned.m16n8k32.row.col.s32.u8.s8.s32 "
        "{%0,%1,%2,%3},{%4,%5,%6,%7},{%8,%9},{%0,%1,%2,%3};"
        : "+r"(d[0]), "+r"(d[1]), "+r"(d[2]), "+r"(d[3])
        : "r"(a[0]), "r"(a[1]), "r"(a[2]), "r"(a[3]), "r"(b[0]), "r"(b[1]));
}
__device__ __forceinline__ void mma_s8s8(int* d, const unsigned* a, const unsigned* b) {
    asm volatile(
        "mma.sync.aligned.m16n8k32.row.col.s32.s8.s8.s32 "
        "{%0,%1,%2,%3},{%4,%5,%6,%7},{%8,%9},{%0,%1,%2,%3};"
        : "+r"(d[0]), "+r"(d[1]), "+r"(d[2]), "+r"(d[3])
        : "r"(a[0]), "r"(a[1]), "r"(a[2]), "r"(a[3]), "r"(b[0]), "r"(b[1]));
}
__device__ __forceinline__ void ldsm_x4(unsigned* r, unsigned addr) {
    asm volatile("ldmatrix.sync.aligned.m8n8.x4.shared.b16 {%0,%1,%2,%3},[%4];"
                 : "=r"(r[0]), "=r"(r[1]), "=r"(r[2]), "=r"(r[3]) : "r"(addr));
}
__device__ __forceinline__ void ldsm_x2(unsigned* r, unsigned addr) {
    asm volatile("ldmatrix.sync.aligned.m8n8.x2.shared.b16 {%0,%1},[%2];"
                 : "=r"(r[0]), "=r"(r[1]) : "r"(addr));
}

// ---------------- dtype detection (inline per block) ----------------
__device__ __forceinline__ int classify_word(unsigned w) {
    if (w == 0u) return -1;
    int iv = (int)w;
    if (iv >= -520 && iv <= 520) return 0;
    float f = __int_as_float(w);
    if (isfinite(f) && fabsf(f) <= 520.0f && f != 0.0f && f == rintf(f)) return 1;
    return 2;
}
__device__ int detect_dtype(const unsigned* w, int nwords) {
    __shared__ int votes[3];
    if (threadIdx.x < 3) votes[threadIdx.x] = 0;
    __syncthreads();
    int local[3] = {0,0,0};
    for (int i = threadIdx.x; i < nwords; i += blockDim.x) {
        int c = classify_word(w[i]);
        if (c >= 0) local[c]++;
    }
    for (int c = 0; c < 3; c++) if (local[c]) atomicAdd(&votes[c], local[c]);
    __syncthreads();
    int best = 0;
    if (votes[1] > votes[best]) best = 1;
    if (votes[2] > votes[best]) best = 2;
    return best;
}

// ---------------- canonicalize x -> u8x4 words ----------------
__global__ void conv_x_kernel(const void* __restrict__ xp) {
    int flag = detect_dtype((const unsigned*)xp, 1024);
    int i = blockIdx.x * blockDim.x + threadIdx.x;
    if (i >= MTOT * (HID/4)) return;
    unsigned a, b, c, d;
    if (flag == 1) {
        float4 v = reinterpret_cast<const float4*>(xp)[i];
        a = (unsigned)(int)v.x; b = (unsigned)(int)v.y;
        c = (unsigned)(int)v.z; d = (unsigned)(int)v.w;
    } else {
        int4 v = reinterpret_cast<const int4*>(xp)[i];
        a = (unsigned)v.x; b = (unsigned)v.y; c = (unsigned)v.z; d = (unsigned)v.w;
    }
    g_x4[i] = (a & 255u) | ((b & 255u) << 8) | ((c & 255u) << 16) | ((d & 255u) << 24);
}

// ---------------- fused convert+transpose+pack weights AND biases ----------------
#define WBLOCKS ((HID*(HID/4) + 255)/256)    // 4096
__global__ void convpack_wb_kernel(const void* w0, const void* w1, const void* w2, const void* w3,
                                   const void* b0, const void* b1, const void* b2, const void* b3) {
    int slot = blockIdx.y;
    const void* ws[4] = {w0, w1, w2, w3};
    const void* bs[4] = {b0, b1, b2, b3};
    if ((int)blockIdx.x < WBLOCKS) {
        const void* wp = ws[slot];
        int flag = detect_dtype((const unsigned*)wp, 1024);
        int i = blockIdx.x * blockDim.x + threadIdx.x;
        if (i >= HID * (HID/4)) return;
        int kw = i >> 11;
        int n  = i & (HID-1);
        unsigned b[4];
        if (flag == 2) {
            const unsigned char* p = (const unsigned char*)wp;
#pragma unroll
            for (int j = 0; j < 4; j++) b[j] = p[(size_t)(4*kw+j)*HID + n];
        } else if (flag == 1) {
            const float* p = (const float*)wp;
#pragma unroll
            for (int j = 0; j < 4; j++) b[j] = (unsigned)(int)p[(size_t)(4*kw+j)*HID + n] & 255u;
        } else {
            const int* p = (const int*)wp;
#pragma unroll
            for (int j = 0; j < 4; j++) b[j] = (unsigned)p[(size_t)(4*kw+j)*HID + n] & 255u;
        }
        g_wt[(size_t)slot * (HID*(HID/4)) + (size_t)n*(HID/4) + kw] =
            b[0] | (b[1]<<8) | (b[2]<<16) | (b[3]<<24);
    } else {
        const void* bp = bs[slot];
        int flag = detect_dtype((const unsigned*)bp, 512);
        int i = ((int)blockIdx.x - WBLOCKS) * blockDim.x + threadIdx.x;
        if (i >= HID) return;
        int v;
        if (flag == 1) v = (int)reinterpret_cast<const float*>(bp)[i];
        else           v = reinterpret_cast<const int*>(bp)[i];
        g_b32[slot * HID + i] = v;
    }
}

// ---------------- QKV projection via IMMA (u8 x s8, exact) ----------------
__global__ __launch_bounds__(256) void proj_imma_kernel() {
    __shared__ unsigned char As[128*80];
    __shared__ unsigned char Bs[128*80];
    int slot = blockIdx.z;
    const unsigned* W4 = g_wt + (size_t)slot * (HID*(HID/4));
    const int* bias = g_b32 + slot * HID;
    int* outp = (slot == 0) ? g_q : (slot == 1) ? g_k : g_v;

    int bn = blockIdx.x;
    int bm = blockIdx.y;
    int t = threadIdx.x, lane = t & 31, warp = t >> 5;
    int wm = warp >> 2, wn = warp & 3;

    unsigned aBase = (unsigned)__cvta_generic_to_shared(As);
    unsigned bBase = (unsigned)__cvta_generic_to_shared(Bs);

    int acc[4][4][4];
#pragma unroll
    for (int i = 0; i < 4; i++)
#pragma unroll
        for (int j = 0; j < 4; j++)
#pragma unroll
            for (int r = 0; r < 4; r++) acc[i][j][r] = 0;

    int lrowA = (lane & 7) + ((lane >> 3) & 1) * 8;
    int lkoffA = (lane >= 16) ? 16 : 0;
    int lrowB = (lane & 7);
    int lkoffB = ((lane >> 3) & 1) * 16;

    for (int ks = 0; ks < 32; ks++) {
        for (int idx = t; idx < 512; idx += 256) {
            int row = idx >> 2, q = idx & 3;
            int4 v = *reinterpret_cast<const int4*>(&g_x4[(size_t)(bm*128 + row)*512 + ks*16 + q*4]);
            *reinterpret_cast<int4*>(As + row*80 + q*16) = v;
            int4 w = *reinterpret_cast<const int4*>(&W4[(size_t)(bn*128 + row)*512 + ks*16 + q*4]);
            *reinterpret_cast<int4*>(Bs + row*80 + q*16) = w;
        }
        __syncthreads();
#pragma unroll
        for (int kk = 0; kk < 2; kk++) {
            unsigned bfr[4][2];
#pragma unroll
            for (int nf = 0; nf < 4; nf++)
                ldsm_x2(bfr[nf], bBase + (wn*32 + nf*8 + lrowB)*80 + kk*32 + lkoffB);
            unsigned afr[4][4];
#pragma unroll
            for (int mf = 0; mf < 4; mf++)
                ldsm_x4(afr[mf], aBase + (wm*64 + mf*16 + lrowA)*80 + kk*32 + lkoffA);
#pragma unroll
            for (int mf = 0; mf < 4; mf++)
#pragma unroll
                for (int nf = 0; nf < 4; nf++)
                    mma_u8s8(acc[mf][nf], afr[mf], bfr[nf]);
        }
        __syncthreads();
    }

#pragma unroll
    for (int mf = 0; mf < 4; mf++) {
#pragma unroll
        for (int nf = 0; nf < 4; nf++) {
            int n = bn*128 + wn*32 + nf*8 + 2*(lane & 3);
            int h = n >> 7, d = n & (HD-1);
            int bia0 = bias[n], bia1 = bias[n+1];
#pragma unroll
            for (int half = 0; half < 2; half++) {
                int r = bm*128 + wm*64 + mf*16 + (lane >> 2) + half*8;
                int b = r >> 11, s = r & (SEQ-1);
                int v0 = (acc[mf][nf][half*2+0] + bia0) >> 6;
                int v1 = (acc[mf][nf][half*2+1] + bia1) >> 6;
                *reinterpret_cast<int2*>(&outp[((size_t)(b*NH + h)*SEQ + s)*HD + d]) = make_int2(v0, v1);
            }
        }
    }
}

// ---------------- QK scores: causal-blocked 128x128 IMAD GEMM, 8x8 regs ----------------
__global__ __launch_bounds__(256) void qk_gemm_kernel() {
    __shared__ int As[32][132];
    __shared__ int Bs[32][132];

    int bh = blockIdx.y;
    int blk = blockIdx.x;                      // 0..135 lower-triangle tiles
    int qi = (int)((sqrtf(8.0f*blk + 1.0f) - 1.0f) * 0.5f);
    while ((qi+1)*(qi+2)/2 <= blk) qi++;
    while (qi*(qi+1)/2 > blk) qi--;
    int ki = blk - qi*(qi+1)/2;

    const int* Qb = g_q + (size_t)bh*SEQ*HD + (size_t)(qi*128)*HD;
    const int* Kb = g_k + (size_t)bh*SEQ*HD + (size_t)(ki*128)*HD;
    int t = threadIdx.x;
    int rg = t >> 4, cg = t & 15;              // 16x16 grid, 8x8 each

    unsigned acc[8][8];
#pragma unroll
    for (int i = 0; i < 8; i++)
#pragma unroll
        for (int j = 0; j < 8; j++) acc[i][j] = 0u;

    for (int ch = 0; ch < 4; ch++) {           // 4 chunks of 32 dims
        // stage transposed: As[d][row], Bs[d][col]
        for (int i = t; i < 128*8; i += 256) {
            int row = i >> 3, g = i & 7;
            int4 qv = *reinterpret_cast<const int4*>(&Qb[row*HD + ch*32 + g*4]);
            As[g*4+0][row] = qv.x; As[g*4+1][row] = qv.y;
            As[g*4+2][row] = qv.z; As[g*4+3][row] = qv.w;
            int4 kv = *reinterpret_cast<const int4*>(&Kb[row*HD + ch*32 + g*4]);
            Bs[g*4+0][row] = kv.x; Bs[g*4+1][row] = kv.y;
            Bs[g*4+2][row] = kv.z; Bs[g*4+3][row] = kv.w;
        }
        __syncthreads();

#pragma unroll 4
        for (int d = 0; d < 32; d++) {
            int4 av0 = *reinterpret_cast<const int4*>(&As[d][rg*8]);
            int4 av1 = *reinterpret_cast<const int4*>(&As[d][rg*8+4]);
            int4 bv0 = *reinterpret_cast<const int4*>(&Bs[d][cg*8]);
            int4 bv1 = *reinterpret_cast<const int4*>(&Bs[d][cg*8+4]);
            int a[8] = {av0.x, av0.y, av0.z, av0.w, av1.x, av1.y, av1.z, av1.w};
            int b[8] = {bv0.x, bv0.y, bv0.z, bv0.w, bv1.x, bv1.y, bv1.z, bv1.w};
#pragma unroll
            for (int i = 0; i < 8; i++)
#pragma unroll
                for (int j = 0; j < 8; j++)
                    acc[i][j] += (unsigned)a[i] * (unsigned)b[j];
        }
        __syncthreads();
    }

    int* dst = g_scores + (size_t)bh*SEQ*SEQ + (size_t)(qi*128 + rg*8)*SEQ + ki*128 + cg*8;
#pragma unroll
    for (int i = 0; i < 8; i++) {
        *reinterpret_cast<int4*>(dst + (size_t)i*SEQ) =
            make_int4(((int)acc[i][0]) >> 1, ((int)acc[i][1]) >> 1,
                      ((int)acc[i][2]) >> 1, ((int)acc[i][3]) >> 1);
        *reinterpret_cast<int4*>(dst + (size_t)i*SEQ + 4) =
            make_int4(((int)acc[i][4]) >> 1, ((int)acc[i][5]) >> 1,
                      ((int)acc[i][6]) >> 1, ((int)acc[i][7]) >> 1);
    }
}

// ---------------- rowmax + sparse AV (warp per row) -> signed digit planes ----------------
__global__ __launch_bounds__(256) void av_kernel() {
    int t = threadIdx.x, lane = t & 31, warp = t >> 5;
    int bh = blockIdx.y;
    int qr = blockIdx.x * 8 + warp;
    const int* srow = g_scores + (size_t)bh*SEQ*SEQ + (size_t)qr*SEQ;
    const int* Vb = g_v + (size_t)bh * SEQ * HD;

    int m = (int)0x80000000;
    for (int k0 = 0; k0 <= qr; k0 += 32) {
        int k = k0 + lane;
        if (k <= qr) m = max(m, srow[k]);
    }
#pragma unroll
    for (int off = 16; off; off >>= 1) m = max(m, __shfl_xor_sync(0xffffffffu, m, off));
    bool hasMasked = (qr < SEQ - 1);
    if (hasMasked) m = max(m, NEGMASK);

    unsigned acc[4] = {0u, 0u, 0u, 0u};
    int d0 = lane * 4;

    for (int k0 = 0; k0 <= qr; k0 += 32) {
        int k = k0 + lane;
        int a = (k <= qr) ? (srow[k] - m + 256) : 0;
        if (a > 4095) a = 4095;
        unsigned mask = __ballot_sync(0xffffffffu, a > 0);
        while (mask) {
            int src = __ffs(mask) - 1;
            mask &= mask - 1;
            unsigned aa = (unsigned)__shfl_sync(0xffffffffu, a, src);
            int kk = k0 + src;
            int4 v = *reinterpret_cast<const int4*>(&Vb[kk*HD + d0]);
            acc[0] += aa * (unsigned)v.x; acc[1] += aa * (unsigned)v.y;
            acc[2] += aa * (unsigned)v.z; acc[3] += aa * (unsigned)v.w;
        }
    }

    int am = NEGMASK - m + 256;
    if (am > 4095) am = 4095;
    if (hasMasked && am > 0) {
        for (int k = qr + 1; k < SEQ; k++) {
            int4 v = *reinterpret_cast<const int4*>(&Vb[k*HD + d0]);
            unsigned ua = (unsigned)am;
            acc[0] += ua * (unsigned)v.x; acc[1] += ua * (unsigned)v.y;
            acc[2] += ua * (unsigned)v.z; acc[3] += ua * (unsigned)v.w;
        }
    }

    // signed base-256 digits of ctx = (int)acc >> 12  (20-bit value)
    unsigned p0 = 0, p1 = 0, p2 = 0;
#pragma unroll
    for (int j = 0; j < 4; j++) {
        int v = ((int)acc[j]) >> 12;
        int dd0 = (int)(signed char)(v & 0xff);
        int r1 = (v - dd0) >> 8;
        int dd1 = (int)(signed char)(r1 & 0xff);
        int dd2 = (r1 - dd1) >> 8;
        p0 |= ((unsigned)dd0 & 255u) << (8*j);
        p1 |= ((unsigned)dd1 & 255u) << (8*j);
        p2 |= ((unsigned)dd2 & 255u) << (8*j);
    }
    int b = bh >> 4, h = bh & (NH-1);
    size_t off = (((size_t)(b*SEQ + qr))*HID + h*HD + d0) >> 2;
    reinterpret_cast<unsigned*>(g_d0)[off] = p0;
    reinterpret_cast<unsigned*>(g_d1)[off] = p1;
    reinterpret_cast<unsigned*>(g_d2)[off] = p2;
}

// ---------------- output projection via IMMA digit planes (exact mod 2^32) ----------------
__global__ __launch_bounds__(256) void out_imma_kernel(float* __restrict__ out) {
    __shared__ unsigned char Ap[3][64*48];
    __shared__ unsigned char Bs[64*48];
    const unsigned* W4 = g_wt + (size_t)3 * (HID*(HID/4));
    const int* bias = g_b32 + 3 * HID;

    int bn = blockIdx.x;
    int bm = blockIdx.y;
    int t = threadIdx.x, lane = t & 31, warp = t >> 5;
    int wm = warp >> 2, wn = warp & 3;

    unsigned aBase[3], bBase;
#pragma unroll
    for (int l = 0; l < 3; l++) aBase[l] = (unsigned)__cvta_generic_to_shared(Ap[l]);
    bBase = (unsigned)__cvta_generic_to_shared(Bs);

    int acc[2][2][3][4];
#pragma unroll
    for (int i = 0; i < 2; i++)
#pragma unroll
        for (int j = 0; j < 2; j++)
#pragma unroll
            for (int l = 0; l < 3; l++)
#pragma unroll
                for (int r = 0; r < 4; r++) acc[i][j][l][r] = 0;

    int lrowA = (lane & 7) + ((lane >> 3) & 1) * 8;
    int lkoffA = (lane >= 16) ? 16 : 0;
    int lrowB = (lane & 7);
    int lkoffB = ((lane >> 3) & 1) * 16;

    const unsigned* P[3] = {reinterpret_cast<const unsigned*>(g_d0),
                            reinterpret_cast<const unsigned*>(g_d1),
                            reinterpret_cast<const unsigned*>(g_d2)};

    for (int ks = 0; ks < 64; ks++) {
        for (int idx = t; idx < 1536; idx += 256) {
            int l = idx >> 9, j = idx & 511, row = j >> 3, q = j & 7;
            unsigned w = P[l][(((size_t)(bm*64 + row))*HID + ks*32 + q*4) >> 2];
            *reinterpret_cast<unsigned*>(Ap[l] + row*48 + q*4) = w;
        }
        for (int idx = t; idx < 128; idx += 256) {
            int row = idx >> 1, q = idx & 1;
            int4 w = *reinterpret_cast<const int4*>(&W4[(size_t)(bn*64 + row)*512 + ks*8 + q*4]);
            *reinterpret_cast<int4*>(Bs + row*48 + q*16) = w;
        }
        __syncthreads();

        unsigned bfr[2][2];
#pragma unroll
        for (int nf = 0; nf < 2; nf++)
            ldsm_x2(bfr[nf], bBase + (wn*16 + nf*8 + lrowB)*48 + lkoffB);
#pragma unroll
        for (int mf = 0; mf < 2; mf++) {
#pragma unroll
            for (int l = 0; l < 3; l++) {
                unsigned afr[4];
                ldsm_x4(afr, aBase[l] + (wm*32 + mf*16 + lrowA)*48 + lkoffA);
#pragma unroll
                for (int nf = 0; nf < 2; nf++)
                    mma_s8s8(acc[mf][nf][l], afr, bfr[nf]);
            }
        }
        __syncthreads();
    }

#pragma unroll
    for (int mf = 0; mf < 2; mf++) {
#pragma unroll
        for (int nf = 0; nf < 2; nf++) {
            int n = bn*64 + wn*16 + nf*8 + 2*(lane & 3);
            unsigned bia0 = (unsigned)bias[n], bia1 = (unsigned)bias[n+1];
#pragma unroll
            for (int half = 0; half < 2; half++) {
                int r = bm*64 + wm*32 + mf*16 + (lane >> 2) + half*8;
                unsigned u0 = (unsigned)acc[mf][nf][0][half*2+0]
                            + ((unsigned)acc[mf][nf][1][half*2+0] << 8)
                            + ((unsigned)acc[mf][nf][2][half*2+0] << 16) + bia0;
                unsigned u1 = (unsigned)acc[mf][nf][0][half*2+1]
                            + ((unsigned)acc[mf][nf][1][half*2+1] << 8)
                            + ((unsigned)acc[mf][nf][2][half*2+1] << 16) + bia1;
                float2 fv = make_float2((float)(((int)u0) >> 7), (float)(((int)u1) >> 7));
                *reinterpret_cast<float2*>(&out[(size_t)r*HID + n]) = fv;
            }
        }
    }
}

// ---------------- launch ----------------
extern "C" void kernel_launch(void* const* d_in, const int* in_sizes, int n_in,
                              void* d_out, int out_size) {
    const void* x  = d_in[0];
    const void* wq = d_in[1]; const void* bq = d_in[2];
    const void* wk = d_in[3]; const void* bk = d_in[4];
    const void* wv = d_in[5]; const void* bv = d_in[6];
    const void* wo = d_in[7]; const void* bo = d_in[8];
    float* out = (float*)d_out;

    conv_x_kernel<<<(MTOT*(HID/4) + 255)/256, 256>>>(x);                              // 1
    convpack_wb_kernel<<<dim3(WBLOCKS + 8, 4), 256>>>(wq, wk, wv, wo, bq, bk, bv, bo);// 2
    proj_imma_kernel<<<dim3(16, 32, 3), 256>>>();                                     // 3
    qk_gemm_kernel<<<dim3(NTRI, BH), 256>>>();                                        // 4 (profiled)
    av_kernel<<<dim3(SEQ/8, BH), 256>>>();                                            // 5
    out_imma_kernel<<<dim3(32, 64), 256>>>(out);                                      // 6
}

// round 11
// speedup vs baseline: 2.2346x; 1.0262x over previous
#include <cuda_runtime.h>
#include <cstdint>
#include <math.h>

#define SEQ 2048
#define HID 2048
#define NB  2
#define NH  16
#define HD  128
#define BH  (NB*NH)          // 32
#define MTOT (NB*SEQ)        // 4096
#define NEGMASK (-(1<<20))
#define NQB (SEQ/128)        // 16
#define NTRI (NQB*(NQB+1)/2) // 136

// ---------------- device scratch ----------------
__device__ unsigned g_x4[MTOT * (HID/4)];
__device__ int g_b32[4 * HID];
__device__ unsigned g_wt[4 * HID * (HID/4)];
__device__ int g_q[BH * SEQ * HD];
__device__ int g_k[BH * SEQ * HD];
__device__ int g_v[BH * SEQ * HD];
__device__ int g_scores[(size_t)BH * SEQ * SEQ];
__device__ unsigned char g_d0[MTOT * HID];
__device__ unsigned char g_d1[MTOT * HID];
__device__ unsigned char g_d2[MTOT * HID];

// ---------------- helpers ----------------
__device__ __forceinline__ void mma_u8s8(int* d, const unsigned* a, const unsigned* b) {
    asm volatile(
        "mma.sync.aligned.m16n8k32.row.col.s32.u8.s8.s32 "
        "{%0,%1,%2,%3},{%4,%5,%6,%7},{%8,%9},{%0,%1,%2,%3};"
        : "+r"(d[0]), "+r"(d[1]), "+r"(d[2]), "+r"(d[3])
        : "r"(a[0]), "r"(a[1]), "r"(a[2]), "r"(a[3]), "r"(b[0]), "r"(b[1]));
}
__device__ __forceinline__ void mma_s8s8(int* d, const unsigned* a, const unsigned* b) {
    asm volatile(
        "mma.sync.aligned.m16n8k32.row.col.s32.s8.s8.s32 "
        "{%0,%1,%2,%3},{%4,%5,%6,%7},{%8,%9},{%0,%1,%2,%3};"
        : "+r"(d[0]), "+r"(d[1]), "+r"(d[2]), "+r"(d[3])
        : "r"(a[0]), "r"(a[1]), "r"(a[2]), "r"(a[3]), "r"(b[0]), "r"(b[1]));
}
__device__ __forceinline__ void ldsm_x4(unsigned* r, unsigned addr) {
    asm volatile("ldmatrix.sync.aligned.m8n8.x4.shared.b16 {%0,%1,%2,%3},[%4];"
                 : "=r"(r[0]), "=r"(r[1]), "=r"(r[2]), "=r"(r[3]) : "r"(addr));
}
__device__ __forceinline__ void ldsm_x2(unsigned* r, unsigned addr) {
    asm volatile("ldmatrix.sync.aligned.m8n8.x2.shared.b16 {%0,%1},[%2];"
                 : "=r"(r[0]), "=r"(r[1]) : "r"(addr));
}
__device__ __forceinline__ void cp16(unsigned smaddr, const void* g) {
    asm volatile("cp.async.cg.shared.global [%0], [%1], 16;" :: "r"(smaddr), "l"(g));
}
#define CP_COMMIT() asm volatile("cp.async.commit_group;" ::: "memory")
#define CP_WAIT1()  asm volatile("cp.async.wait_group 1;" ::: "memory")
#define CP_WAIT0()  asm volatile("cp.async.wait_group 0;" ::: "memory")

// ---------------- dtype detection ----------------
__device__ __forceinline__ int classify_word(unsigned w) {
    if (w == 0u) return -1;
    int iv = (int)w;
    if (iv >= -520 && iv <= 520) return 0;
    float f = __int_as_float(w);
    if (isfinite(f) && fabsf(f) <= 520.0f && f != 0.0f && f == rintf(f)) return 1;
    return 2;
}
__device__ int detect_dtype(const unsigned* w, int nwords) {
    __shared__ int votes[3];
    if (threadIdx.x < 3) votes[threadIdx.x] = 0;
    __syncthreads();
    int local[3] = {0,0,0};
    for (int i = threadIdx.x; i < nwords; i += blockDim.x) {
        int c = classify_word(w[i]);
        if (c >= 0) local[c]++;
    }
    for (int c = 0; c < 3; c++) if (local[c]) atomicAdd(&votes[c], local[c]);
    __syncthreads();
    int best = 0;
    if (votes[1] > votes[best]) best = 1;
    if (votes[2] > votes[best]) best = 2;
    return best;
}

// ---------------- canonicalize x ----------------
__global__ void conv_x_kernel(const void* __restrict__ xp) {
    int flag = detect_dtype((const unsigned*)xp, 1024);
    int i = blockIdx.x * blockDim.x + threadIdx.x;
    if (i >= MTOT * (HID/4)) return;
    unsigned a, b, c, d;
    if (flag == 1) {
        float4 v = reinterpret_cast<const float4*>(xp)[i];
        a = (unsigned)(int)v.x; b = (unsigned)(int)v.y;
        c = (unsigned)(int)v.z; d = (unsigned)(int)v.w;
    } else {
        int4 v = reinterpret_cast<const int4*>(xp)[i];
        a = (unsigned)v.x; b = (unsigned)v.y; c = (unsigned)v.z; d = (unsigned)v.w;
    }
    g_x4[i] = (a & 255u) | ((b & 255u) << 8) | ((c & 255u) << 16) | ((d & 255u) << 24);
}

// ---------------- convert+transpose+pack weights ----------------
__global__ void convpack_w_kernel(const void* w0, const void* w1, const void* w2, const void* w3) {
    int slot = blockIdx.y;
    const void* ws[4] = {w0, w1, w2, w3};
    const void* wp = ws[slot];
    int flag = detect_dtype((const unsigned*)wp, 1024);
    int i = blockIdx.x * blockDim.x + threadIdx.x;
    if (i >= HID * (HID/4)) return;
    int kw = i >> 11;
    int n  = i & (HID-1);
    unsigned b[4];
    if (flag == 2) {
        const unsigned char* p = (const unsigned char*)wp;
#pragma unroll
        for (int j = 0; j < 4; j++) b[j] = p[(size_t)(4*kw+j)*HID + n];
    } else if (flag == 1) {
        const float* p = (const float*)wp;
#pragma unroll
        for (int j = 0; j < 4; j++) b[j] = (unsigned)(int)p[(size_t)(4*kw+j)*HID + n] & 255u;
    } else {
        const int* p = (const int*)wp;
#pragma unroll
        for (int j = 0; j < 4; j++) b[j] = (unsigned)p[(size_t)(4*kw+j)*HID + n] & 255u;
    }
    g_wt[(size_t)slot * (HID*(HID/4)) + (size_t)n*(HID/4) + kw] =
        b[0] | (b[1]<<8) | (b[2]<<16) | (b[3]<<24);
}

// ---------------- biases ----------------
__global__ void conv_b_kernel(const void* b0, const void* b1, const void* b2, const void* b3) {
    int slot = blockIdx.y;
    const void* bs[4] = {b0, b1, b2, b3};
    int flag = detect_dtype((const unsigned*)bs[slot], 512);
    int i = blockIdx.x * blockDim.x + threadIdx.x;
    if (i >= HID) return;
    int v;
    if (flag == 1) v = (int)reinterpret_cast<const float*>(bs[slot])[i];
    else           v = reinterpret_cast<const int*>(bs[slot])[i];
    g_b32[slot * HID + i] = v;
}

// ---------------- QKV projection: IMMA + cp.async double buffer ----------------
__global__ __launch_bounds__(256) void proj_imma_kernel() {
    __shared__ unsigned char As[2][128*80];
    __shared__ unsigned char Bs[2][128*80];
    int slot = blockIdx.z;
    const unsigned* W4 = g_wt + (size_t)slot * (HID*(HID/4));
    const int* bias = g_b32 + slot * HID;
    int* outp = (slot == 0) ? g_q : (slot == 1) ? g_k : g_v;

    int bn = blockIdx.x;
    int bm = blockIdx.y;
    int t = threadIdx.x, lane = t & 31, warp = t >> 5;
    int wm = warp >> 2, wn = warp & 3;

    unsigned aB = (unsigned)__cvta_generic_to_shared(As);
    unsigned bB = (unsigned)__cvta_generic_to_shared(Bs);

    int acc[4][4][4];
#pragma unroll
    for (int i = 0; i < 4; i++)
#pragma unroll
        for (int j = 0; j < 4; j++)
#pragma unroll
            for (int r = 0; r < 4; r++) acc[i][j][r] = 0;

    int lrowA = (lane & 7) + ((lane >> 3) & 1) * 8;
    int lkoffA = (lane >= 16) ? 16 : 0;
    int lrowB = (lane & 7);
    int lkoffB = ((lane >> 3) & 1) * 16;

    // stage ks into buffer buf (2 iterations x 2 cp16 per thread)
    #define PJ_STAGE(ks, buf)                                                              \
        do {                                                                               \
            for (int idx = t; idx < 512; idx += 256) {                                     \
                int row = idx >> 2, q = idx & 3;                                           \
                cp16(aB + (buf)*10240 + row*80 + q*16,                                     \
                     &g_x4[(size_t)(bm*128 + row)*512 + (ks)*16 + q*4]);                   \
                cp16(bB + (buf)*10240 + row*80 + q*16,                                     \
                     &W4[(size_t)(bn*128 + row)*512 + (ks)*16 + q*4]);                     \
            }                                                                              \
            CP_COMMIT();                                                                   \
        } while (0)

    PJ_STAGE(0, 0);
    for (int ks = 0; ks < 32; ks++) {
        int buf = ks & 1;
        if (ks < 31) { PJ_STAGE(ks + 1, buf ^ 1); CP_WAIT1(); }
        else         { CP_WAIT0(); }
        __syncthreads();
#pragma unroll
        for (int kk = 0; kk < 2; kk++) {
            unsigned bfr[4][2];
#pragma unroll
            for (int nf = 0; nf < 4; nf++)
                ldsm_x2(bfr[nf], bB + buf*10240 + (wn*32 + nf*8 + lrowB)*80 + kk*32 + lkoffB);
            unsigned afr[4][4];
#pragma unroll
            for (int mf = 0; mf < 4; mf++)
                ldsm_x4(afr[mf], aB + buf*10240 + (wm*64 + mf*16 + lrowA)*80 + kk*32 + lkoffA);
#pragma unroll
            for (int mf = 0; mf < 4; mf++)
#pragma unroll
                for (int nf = 0; nf < 4; nf++)
                    mma_u8s8(acc[mf][nf], afr[mf], bfr[nf]);
        }
        __syncthreads();
    }
    #undef PJ_STAGE

#pragma unroll
    for (int mf = 0; mf < 4; mf++) {
#pragma unroll
        for (int nf = 0; nf < 4; nf++) {
            int n = bn*128 + wn*32 + nf*8 + 2*(lane & 3);
            int h = n >> 7, d = n & (HD-1);
            int bia0 = bias[n], bia1 = bias[n+1];
#pragma unroll
            for (int half = 0; half < 2; half++) {
                int r = bm*128 + wm*64 + mf*16 + (lane >> 2) + half*8;
                int b = r >> 11, s = r & (SEQ-1);
                int v0 = (acc[mf][nf][half*2+0] + bia0) >> 6;
                int v1 = (acc[mf][nf][half*2+1] + bia1) >> 6;
                *reinterpret_cast<int2*>(&outp[((size_t)(b*NH + h)*SEQ + s)*HD + d]) = make_int2(v0, v1);
            }
        }
    }
}

// ---------------- QK scores: 128x128 IMAD, 8x8 regs ----------------
__global__ __launch_bounds__(256) void qk_gemm_kernel() {
    __shared__ int As[32][132];
    __shared__ int Bs[32][132];

    int bh = blockIdx.y;
    int blk = blockIdx.x;
    int qi = (int)((sqrtf(8.0f*blk + 1.0f) - 1.0f) * 0.5f);
    while ((qi+1)*(qi+2)/2 <= blk) qi++;
    while (qi*(qi+1)/2 > blk) qi--;
    int ki = blk - qi*(qi+1)/2;

    const int* Qb = g_q + (size_t)bh*SEQ*HD + (size_t)(qi*128)*HD;
    const int* Kb = g_k + (size_t)bh*SEQ*HD + (size_t)(ki*128)*HD;
    int t = threadIdx.x;
    int rg = t >> 4, cg = t & 15;

    unsigned acc[8][8];
#pragma unroll
    for (int i = 0; i < 8; i++)
#pragma unroll
        for (int j = 0; j < 8; j++) acc[i][j] = 0u;

    for (int ch = 0; ch < 4; ch++) {
        for (int i = t; i < 128*8; i += 256) {
            int row = i >> 3, g = i & 7;
            int4 qv = *reinterpret_cast<const int4*>(&Qb[row*HD + ch*32 + g*4]);
            As[g*4+0][row] = qv.x; As[g*4+1][row] = qv.y;
            As[g*4+2][row] = qv.z; As[g*4+3][row] = qv.w;
            int4 kv = *reinterpret_cast<const int4*>(&Kb[row*HD + ch*32 + g*4]);
            Bs[g*4+0][row] = kv.x; Bs[g*4+1][row] = kv.y;
            Bs[g*4+2][row] = kv.z; Bs[g*4+3][row] = kv.w;
        }
        __syncthreads();

#pragma unroll 4
        for (int d = 0; d < 32; d++) {
            int4 av0 = *reinterpret_cast<const int4*>(&As[d][rg*8]);
            int4 av1 = *reinterpret_cast<const int4*>(&As[d][rg*8+4]);
            int4 bv0 = *reinterpret_cast<const int4*>(&Bs[d][cg*8]);
            int4 bv1 = *reinterpret_cast<const int4*>(&Bs[d][cg*8+4]);
            int a[8] = {av0.x, av0.y, av0.z, av0.w, av1.x, av1.y, av1.z, av1.w};
            int b[8] = {bv0.x, bv0.y, bv0.z, bv0.w, bv1.x, bv1.y, bv1.z, bv1.w};
#pragma unroll
            for (int i = 0; i < 8; i++)
#pragma unroll
                for (int j = 0; j < 8; j++)
                    acc[i][j] += (unsigned)a[i] * (unsigned)b[j];
        }
        __syncthreads();
    }

    int* dst = g_scores + (size_t)bh*SEQ*SEQ + (size_t)(qi*128 + rg*8)*SEQ + ki*128 + cg*8;
#pragma unroll
    for (int i = 0; i < 8; i++) {
        *reinterpret_cast<int4*>(dst + (size_t)i*SEQ) =
            make_int4(((int)acc[i][0]) >> 1, ((int)acc[i][1]) >> 1,
                      ((int)acc[i][2]) >> 1, ((int)acc[i][3]) >> 1);
        *reinterpret_cast<int4*>(dst + (size_t)i*SEQ + 4) =
            make_int4(((int)acc[i][4]) >> 1, ((int)acc[i][5]) >> 1,
                      ((int)acc[i][6]) >> 1, ((int)acc[i][7]) >> 1);
    }
}

// ---------------- rowmax + sparse AV -> digit planes ----------------
__global__ __launch_bounds__(256) void av_kernel() {
    int t = threadIdx.x, lane = t & 31, warp = t >> 5;
    int bh = blockIdx.y;
    int qr = blockIdx.x * 8 + warp;
    const int* srow = g_scores + (size_t)bh*SEQ*SEQ + (size_t)qr*SEQ;
    const int* Vb = g_v + (size_t)bh * SEQ * HD;

    int m = (int)0x80000000;
    for (int k0 = 0; k0 <= qr; k0 += 32) {
        int k = k0 + lane;
        if (k <= qr) m = max(m, srow[k]);
    }
#pragma unroll
    for (int off = 16; off; off >>= 1) m = max(m, __shfl_xor_sync(0xffffffffu, m, off));
    bool hasMasked = (qr < SEQ - 1);
    if (hasMasked) m = max(m, NEGMASK);

    unsigned acc[4] = {0u, 0u, 0u, 0u};
    int d0 = lane * 4;

    for (int k0 = 0; k0 <= qr; k0 += 32) {
        int k = k0 + lane;
        int a = (k <= qr) ? (srow[k] - m + 256) : 0;
        if (a > 4095) a = 4095;
        unsigned mask = __ballot_sync(0xffffffffu, a > 0);
        while (mask) {
            int src = __ffs(mask) - 1;
            mask &= mask - 1;
            unsigned aa = (unsigned)__shfl_sync(0xffffffffu, a, src);
            int kk = k0 + src;
            int4 v = *reinterpret_cast<const int4*>(&Vb[kk*HD + d0]);
            acc[0] += aa * (unsigned)v.x; acc[1] += aa * (unsigned)v.y;
            acc[2] += aa * (unsigned)v.z; acc[3] += aa * (unsigned)v.w;
        }
    }

    int am = NEGMASK - m + 256;
    if (am > 4095) am = 4095;
    if (hasMasked && am > 0) {
        for (int k = qr + 1; k < SEQ; k++) {
            int4 v = *reinterpret_cast<const int4*>(&Vb[k*HD + d0]);
            unsigned ua = (unsigned)am;
            acc[0] += ua * (unsigned)v.x; acc[1] += ua * (unsigned)v.y;
            acc[2] += ua * (unsigned)v.z; acc[3] += ua * (unsigned)v.w;
        }
    }

    unsigned p0 = 0, p1 = 0, p2 = 0;
#pragma unroll
    for (int j = 0; j < 4; j++) {
        int v = ((int)acc[j]) >> 12;
        int dd0 = (int)(signed char)(v & 0xff);
        int r1 = (v - dd0) >> 8;
        int dd1 = (int)(signed char)(r1 & 0xff);
        int dd2 = (r1 - dd1) >> 8;
        p0 |= ((unsigned)dd0 & 255u) << (8*j);
        p1 |= ((unsigned)dd1 & 255u) << (8*j);
        p2 |= ((unsigned)dd2 & 255u) << (8*j);
    }
    int b = bh >> 4, h = bh & (NH-1);
    size_t off = (((size_t)(b*SEQ + qr))*HID + h*HD + d0) >> 2;
    reinterpret_cast<unsigned*>(g_d0)[off] = p0;
    reinterpret_cast<unsigned*>(g_d1)[off] = p1;
    reinterpret_cast<unsigned*>(g_d2)[off] = p2;
}

// ---------------- output projection: IMMA digit planes + cp.async double buffer ----------------
__global__ __launch_bounds__(256) void out_imma_kernel(float* __restrict__ out) {
    __shared__ unsigned char Ap[2][3][64*48];
    __shared__ unsigned char Bs[2][64*48];
    const unsigned* W4 = g_wt + (size_t)3 * (HID*(HID/4));
    const int* bias = g_b32 + 3 * HID;

    int bn = blockIdx.x;
    int bm = blockIdx.y;
    int t = threadIdx.x, lane = t & 31, warp = t >> 5;
    int wm = warp >> 2, wn = warp & 3;

    unsigned aB = (unsigned)__cvta_generic_to_shared(Ap);
    unsigned bB = (unsigned)__cvta_generic_to_shared(Bs);

    int acc[2][2][3][4];
#pragma unroll
    for (int i = 0; i < 2; i++)
#pragma unroll
        for (int j = 0; j < 2; j++)
#pragma unroll
            for (int l = 0; l < 3; l++)
#pragma unroll
                for (int r = 0; r < 4; r++) acc[i][j][l][r] = 0;

    int lrowA = (lane & 7) + ((lane >> 3) & 1) * 8;
    int lkoffA = (lane >= 16) ? 16 : 0;
    int lrowB = (lane & 7);
    int lkoffB = ((lane >> 3) & 1) * 16;

    const unsigned char* P[3] = {g_d0, g_d1, g_d2};

    // A: 3 planes x 64 rows x 32B (2x16B); B: 64 rows x 32B
    #define OT_STAGE(ks, buf)                                                              \
        do {                                                                               \
            for (int idx = t; idx < 384; idx += 256) {                                     \
                int l = idx >> 7, j = idx & 127, row = j >> 1, half = j & 1;               \
                cp16(aB + (buf)*9216 + l*3072 + row*48 + half*16,                          \
                     P[l] + ((size_t)(bm*64 + row))*HID + (ks)*32 + half*16);              \
            }                                                                              \
            for (int idx = t; idx < 128; idx += 256) {                                     \
                int row = idx >> 1, half = idx & 1;                                        \
                cp16(bB + (buf)*3072 + row*48 + half*16,                                   \
                     &W4[(size_t)(bn*64 + row)*512 + (ks)*8 + half*4]);                    \
            }                                                                              \
            CP_COMMIT();                                                                   \
        } while (0)

    OT_STAGE(0, 0);
    for (int ks = 0; ks < 64; ks++) {
        int buf = ks & 1;
        if (ks < 63) { OT_STAGE(ks + 1, buf ^ 1); CP_WAIT1(); }
        else         { CP_WAIT0(); }
        __syncthreads();

        unsigned bfr[2][2];
#pragma unroll
        for (int nf = 0; nf < 2; nf++)
            ldsm_x2(bfr[nf], bB + buf*3072 + (wn*16 + nf*8 + lrowB)*48 + lkoffB);
#pragma unroll
        for (int mf = 0; mf < 2; mf++) {
#pragma unroll
            for (int l = 0; l < 3; l++) {
                unsigned afr[4];
                ldsm_x4(afr, aB + buf*9216 + l*3072 + (wm*32 + mf*16 + lrowA)*48 + lkoffA);
#pragma unroll
                for (int nf = 0; nf < 2; nf++)
                    mma_s8s8(acc[mf][nf][l], afr, bfr[nf]);
            }
        }
        __syncthreads();
    }
    #undef OT_STAGE

#pragma unroll
    for (int mf = 0; mf < 2; mf++) {
#pragma unroll
        for (int nf = 0; nf < 2; nf++) {
            int n = bn*64 + wn*16 + nf*8 + 2*(lane & 3);
            unsigned bia0 = (unsigned)bias[n], bia1 = (unsigned)bias[n+1];
#pragma unroll
            for (int half = 0; half < 2; half++) {
                int r = bm*64 + wm*32 + mf*16 + (lane >> 2) + half*8;
                unsigned u0 = (unsigned)acc[mf][nf][0][half*2+0]
                            + ((unsigned)acc[mf][nf][1][half*2+0] << 8)
                            + ((unsigned)acc[mf][nf][2][half*2+0] << 16) + bia0;
                unsigned u1 = (unsigned)acc[mf][nf][0][half*2+1]
                            + ((unsigned)acc[mf][nf][1][half*2+1] << 8)
                            + ((unsigned)acc[mf][nf][2][half*2+1] << 16) + bia1;
                float2 fv = make_float2((float)(((int)u0) >> 7), (float)(((int)u1) >> 7));
                *reinterpret_cast<float2*>(&out[(size_t)r*HID + n]) = fv;
            }
        }
    }
}

// ---------------- launch ----------------
extern "C" void kernel_launch(void* const* d_in, const int* in_sizes, int n_in,
                              void* d_out, int out_size) {
    const void* x  = d_in[0];
    const void* wq = d_in[1]; const void* bq = d_in[2];
    const void* wk = d_in[3]; const void* bk = d_in[4];
    const void* wv = d_in[5]; const void* bv = d_in[6];
    const void* wo = d_in[7]; const void* bo = d_in[8];
    float* out = (float*)d_out;

    conv_x_kernel<<<(MTOT*(HID/4) + 255)/256, 256>>>(x);                              // 1
    convpack_w_kernel<<<dim3((HID*(HID/4) + 255)/256, 4), 256>>>(wq, wk, wv, wo);     // 2
    conv_b_kernel<<<dim3((HID + 255)/256, 4), 256>>>(bq, bk, bv, bo);                 // 3
    proj_imma_kernel<<<dim3(16, 32, 3), 256>>>();                                     // 4 (profiled)
    qk_gemm_kernel<<<dim3(NTRI, BH), 256>>>();                                        // 5
    av_kernel<<<dim3(SEQ/8, BH), 256>>>();                                            // 6
    out_imma_kernel<<<dim3(32, 64), 256>>>(out);                                      // 7
}